// round 14
// baseline (speedup 1.0000x reference)
#include <cuda_runtime.h>
#include <math.h>

#define DINLINE __device__ __forceinline__

// ---------------------------------------------------------------------------
// Fixed problem dimensions (B=4, grid 513, coef 512, epoch=101 -> K=2)
// ---------------------------------------------------------------------------
namespace fns {
constexpr int NB = 4;
constexpr int NG = 513;
constexpr int NI = 511;
constexpr int NC = 512;
constexpr int NK = 258;
constexpr int NK2 = 516;
constexpr long long NN  = (long long)NG * NG;
constexpr long long NCC = (long long)NC * NC;
constexpr long long NII = (long long)NI * NI;
constexpr long long NIG = (long long)NI * NG;
constexpr long long NAF = (long long)NK2 * NK2;  // folded A: 516 x 516
constexpr long long NF  = (long long)NK2 * NI;   // 516 x 511
constexpr int NBLK_A = 128;
constexpr int NBLK_N = 256;
constexpr int KSTEPS = 2;
}
using namespace fns;

// ---------------------------------------------------------------------------
// Static device scratch
// ---------------------------------------------------------------------------
__device__ float  g_x   [NB * NN];
__device__ float  g_x2  [NB * NN];
__device__ float  g_r   [NB * NN];
__device__ float  g_e   [NB * NN];
__device__ float  g_rh  [NB * NN];
__device__ float  g_dinv[NB * NII];
__device__ float  g_S   [NG * (long long)NI];  // S[p][j], ld=NI
__device__ float  g_St  [NIG];                 // St[j][p], ld=NG
__device__ float  g_U   [NB * NIG];            // 511 x 513, ld=NG
__device__ float2 g_cA  [NB * 4 * NN];         // strip scratch stage-1
__device__ float2 g_cB  [NB * 4 * NN];         // strip scratch stage-2
__device__ float2 g_cC  [NB * NN];             // spectral signal
__device__ float2 g_cD  [NB * NN];             // backward-conv output
__device__ float2 g_wf  [NB * 49];             // composed 7x7 forward taps
__device__ float  g_Af  [NB * NAF];            // folded [A1f ; A2f], 516 x 516
__device__ float  g_F   [NB * NF];             // [A ; B], 516 x 511
__device__ float  g_Bm  [NF];                  // [C ; S], 516 x 511 (const)
__device__ float  g_Em  [(long long)NI * NK2]; // [Cos | Sin], 511 x 516 (const)
__device__ double g_pd1 [2048];
__device__ double g_pd2 [2048];
__device__ float  g_alpha[NB];

// ---------------------------------------------------------------------------
// Darcy FEM 9-point stencil (global-memory form, for resid / alpha)
// ---------------------------------------------------------------------------
DINLINE float darcy_at(const float* __restrict__ x,
                       const float* __restrict__ a, int i, int j)
{
    const float c23 = 2.f / 3.f, c16 = -1.f / 6.f, c13 = -1.f / 3.f;
    float s = 0.f;
#pragma unroll
    for (int u = 0; u < 2; u++) {
#pragma unroll
        for (int v = 0; v < 2; v++) {
            int I = i - 1 + u, J = j - 1 + v;
            float av = a[(long long)I * NC + J];
            float k0, k1, k2, k3;
            if (u == 0 && v == 0) { k0 = c16; k1 = c23; k2 = c16; k3 = c13; }
            else if (u == 0 && v == 1) { k0 = c23; k1 = c16; k2 = c13; k3 = c16; }
            else if (u == 1 && v == 0) { k0 = c13; k1 = c16; k2 = c23; k3 = c16; }
            else                        { k0 = c16; k1 = c13; k2 = c16; k3 = c23; }
            s += av * (k3 * x[(long long)I * NG + J]
                     + k2 * x[(long long)I * NG + J + 1]
                     + k0 * x[(long long)(I + 1) * NG + J]
                     + k1 * x[(long long)(I + 1) * NG + J + 1]);
        }
    }
    return s;
}

DINLINE float2 cmad(float2 acc, float2 a, float2 b)
{
    acc.x = fmaf(a.x, b.x, fmaf(-a.y, b.y, acc.x));
    acc.y = fmaf(a.x, b.y, fmaf(a.y, b.x, acc.y));
    return acc;
}

// ---------------------------------------------------------------------------
// One segmented setup kernel: zero x/x2/e, S/St, Bm, Em, dinv
// ---------------------------------------------------------------------------
__global__ void k_setup(float* __restrict__ x, float* __restrict__ x2,
                        float* __restrict__ e,
                        float* __restrict__ S, float* __restrict__ St,
                        float* __restrict__ Bm, float* __restrict__ Em,
                        const float* __restrict__ a, float* __restrict__ dinv)
{
    long long idx = (long long)blockIdx.x * blockDim.x + threadIdx.x;
    const long long T0 = (long long)NB * NN;
    const long long T1 = T0 + (long long)NG * NI;
    const long long T2 = T1 + (long long)NK2 * NI;
    const long long T3 = T2 + (long long)NI * NK2;
    const long long T4 = T3 + (long long)NB * NII;
    if (idx < T0) {
        x[idx] = 0.f; x2[idx] = 0.f; e[idx] = 0.f;
    } else if (idx < T1) {
        long long t = idx - T0;
        int p = (int)(t / NI), j = (int)(t - (long long)p * NI);
        int m = (j + 1) * (p - 256);
        int mm = ((m % 1024) + 1024) % 1024;
        float v = sinpif((float)mm / 512.f);
        S[t] = v;
        St[(long long)j * NG + p] = v;
    } else if (idx < T2) {
        long long t = idx - T1;
        int k2 = (int)(t / NI), s = (int)(t - (long long)k2 * NI);
        int k = (k2 < NK) ? k2 : k2 - NK;
        int tm = (2 * k * s) % 2050;
        float xr = (float)tm / 1025.f;
        Bm[t] = (k2 < NK) ? cospif(xr) : -sinpif(xr);
    } else if (idx < T3) {
        long long t = idx - T2;
        int s = (int)(t / NK2), k2 = (int)(t - (long long)s * NK2);
        int k = (k2 < NK) ? k2 : k2 - NK;
        int tm = (2 * s * k) % 2050;
        float xr = (float)tm / 1025.f;
        Em[t] = (k2 < NK) ? cospif(xr) : sinpif(xr);
    } else if (idx < T4) {
        long long t = idx - T3;
        int b = (int)(t / NII);
        long long rem = t - (long long)b * NII;
        int p = (int)(rem / NI), q = (int)(rem - (long long)p * NI);
        const float* ap = a + (long long)b * NCC;
        float s = ap[(long long)p * NC + q] + ap[(long long)p * NC + q + 1]
                + ap[(long long)(p + 1) * NC + q] + ap[(long long)(p + 1) * NC + q + 1];
        dinv[t] = 1.f / ((2.f / 3.f) * s);
    }
}

// ---------------------------------------------------------------------------
// Compose the 3-stage complex conv chain into one 7x7 tap set.
// ---------------------------------------------------------------------------
__global__ void k_compose(const float* __restrict__ w1r, const float* __restrict__ w1i,
                          const float* __restrict__ w2r, const float* __restrict__ w2i,
                          const float* __restrict__ w3r, const float* __restrict__ w3i,
                          float2* __restrict__ wf)
{
    int b = blockIdx.x;
    int t = threadIdx.x;
    if (t >= 49) return;
    int dy = t / 7, dx = t % 7;
    float accr = 0.f, acci = 0.f;
    for (int c = 0; c < 4; c++) {
        for (int o = 0; o < 4; o++) {
            for (int a = 0; a < 9; a++) {
                int ay = a / 3, ax = a % 3;
                float r1 = w1r[(b * 4 + c) * 9 + a];
                float i1 = w1i[(b * 4 + c) * 9 + a];
                for (int bt = 0; bt < 9; bt++) {
                    int by = bt / 3, bx = bt % 3;
                    int cy = dy - ay - by, cx = dx - ax - bx;
                    if (cy < 0 || cy > 2 || cx < 0 || cx > 2) continue;
                    float r2 = w2r[((b * 4 + o) * 4 + c) * 9 + bt];
                    float i2 = w2i[((b * 4 + o) * 4 + c) * 9 + bt];
                    float r3 = w3r[(b * 4 + o) * 9 + cy * 3 + cx];
                    float i3 = w3i[(b * 4 + o) * 9 + cy * 3 + cx];
                    float tr = r1 * r2 - i1 * i2;
                    float ti = r1 * i2 + i1 * r2;
                    accr += tr * r3 - ti * i3;
                    acci += tr * i3 + ti * r3;
                }
            }
        }
    }
    wf[b * 49 + t] = make_float2(accr, acci);
}

// ---------------------------------------------------------------------------
// Fused Jacobi: 5 sweeps in one kernel via smem (44x44 tile, halo 6).
// Proven R12 form. RESID variant also writes r = f - A(x_final).
// ---------------------------------------------------------------------------
template<bool RESID>
__global__ __launch_bounds__(256)
void k_jacobi5(const float* __restrict__ xin, float* __restrict__ xout,
               const float* __restrict__ f, const float* __restrict__ a,
               const float* __restrict__ dinv, float* __restrict__ rout)
{
    constexpr int W = 44, HALO = 6, SW = 5;
    __shared__ float xs[2][W][W];
    __shared__ float as[W][W], fs[W][W], ds[W][W];
    int b = blockIdx.z;
    int Oi = blockIdx.y * 32, Oj = blockIdx.x * 32;
    const float* xp = xin + (long long)b * NN;
    const float* fp = f + (long long)b * NN;
    const float* ap = a + (long long)b * NCC;
    const float* dp = dinv + (long long)b * NII;
    float* xo = xout + (long long)b * NN;
    int tid = threadIdx.x;

    for (int idx = tid; idx < W * W; idx += 256) {
        int li = idx / W, lj = idx - (idx / W) * W;
        int gi = Oi - HALO + li, gj = Oj - HALO + lj;
        bool inx = (gi >= 0 && gi <= 512 && gj >= 0 && gj <= 512);
        xs[0][li][lj] = inx ? xp[(long long)gi * NG + gj] : 0.f;
        fs[li][lj]    = inx ? fp[(long long)gi * NG + gj] : 0.f;
        bool ina = (gi >= 0 && gi <= 511 && gj >= 0 && gj <= 511);
        as[li][lj] = ina ? ap[(long long)gi * NC + gj] : 0.f;
        bool ind = (gi >= 1 && gi <= 511 && gj >= 1 && gj <= 511);
        ds[li][lj] = ind ? 0.75f * dp[(long long)(gi - 1) * NI + (gj - 1)] : 0.f;
    }
    __syncthreads();

    const float c23 = 2.f / 3.f, c16 = -1.f / 6.f, c13 = -1.f / 3.f;
    int cur = 0;
    for (int s = 1; s <= SW; s++) {
        for (int idx = tid; idx < W * W; idx += 256) {
            int li = idx / W, lj = idx - (idx / W) * W;
            if (li < s || li >= W - s || lj < s || lj >= W - s) continue;
            int gi = Oi - HALO + li, gj = Oj - HALO + lj;
            float old = xs[cur][li][lj];
            float nv = old;
            if (gi >= 1 && gi <= 511 && gj >= 1 && gj <= 511) {
                float sum = 0.f;
#pragma unroll
                for (int u = 0; u < 2; u++) {
#pragma unroll
                    for (int v = 0; v < 2; v++) {
                        float av = as[li - 1 + u][lj - 1 + v];
                        float k0, k1, k2, k3;
                        if (u == 0 && v == 0) { k0 = c16; k1 = c23; k2 = c16; k3 = c13; }
                        else if (u == 0 && v == 1) { k0 = c23; k1 = c16; k2 = c13; k3 = c16; }
                        else if (u == 1 && v == 0) { k0 = c13; k1 = c16; k2 = c23; k3 = c16; }
                        else                        { k0 = c16; k1 = c13; k2 = c16; k3 = c23; }
                        sum += av * (k3 * xs[cur][li - 1 + u][lj - 1 + v]
                                   + k2 * xs[cur][li - 1 + u][lj + v]
                                   + k0 * xs[cur][li + u][lj - 1 + v]
                                   + k1 * xs[cur][li + u][lj + v]);
                    }
                }
                float rr = fs[li][lj] - sum;
                nv = old + ds[li][lj] * rr;
            }
            xs[cur ^ 1][li][lj] = nv;
        }
        __syncthreads();
        cur ^= 1;
    }

    float* rp = RESID ? (rout + (long long)b * NN) : nullptr;
    for (int idx = tid; idx < 32 * 32; idx += 256) {
        int oi = idx / 32, oj = idx - (idx / 32) * 32;
        int gi = Oi + oi, gj = Oj + oj;
        if (gi > 512 || gj > 512) continue;
        int li = HALO + oi, lj = HALO + oj;
        xo[(long long)gi * NG + gj] = xs[cur][li][lj];
        if (RESID) {
            float d = 0.f;
            if (gi >= 1 && gi <= 511 && gj >= 1 && gj <= 511) {
                float sum = 0.f;
#pragma unroll
                for (int u = 0; u < 2; u++) {
#pragma unroll
                    for (int v = 0; v < 2; v++) {
                        float av = as[li - 1 + u][lj - 1 + v];
                        float k0, k1, k2, k3;
                        if (u == 0 && v == 0) { k0 = c16; k1 = c23; k2 = c16; k3 = c13; }
                        else if (u == 0 && v == 1) { k0 = c23; k1 = c16; k2 = c13; k3 = c16; }
                        else if (u == 1 && v == 0) { k0 = c13; k1 = c16; k2 = c23; k3 = c16; }
                        else                        { k0 = c16; k1 = c13; k2 = c16; k3 = c23; }
                        sum += av * (k3 * xs[cur][li - 1 + u][lj - 1 + v]
                                   + k2 * xs[cur][li - 1 + u][lj + v]
                                   + k0 * xs[cur][li + u][lj - 1 + v]
                                   + k1 * xs[cur][li + u][lj + v]);
                    }
                }
                d = sum;
            }
            rp[(long long)gi * NG + gj] = fs[li][lj] - d;
        }
    }
}

__global__ __launch_bounds__(256)
void k_resid(const float* __restrict__ x, const float* __restrict__ f,
             const float* __restrict__ a, float* __restrict__ r)
{
    int b = blockIdx.z;
    int j = blockIdx.x * 16 + threadIdx.x;
    int i = blockIdx.y * 16 + threadIdx.y;
    if (i >= NG || j >= NG) return;
    long long o = (long long)b * NN + (long long)i * NG + j;
    float d = 0.f;
    if (i > 0 && j > 0 && i < NG - 1 && j < NG - 1)
        d = darcy_at(x + (long long)b * NN, a + (long long)b * NCC, i, j);
    r[o] = f[o] - d;
}

// ---------------------------------------------------------------------------
// Real SGEMM, double-buffered, 64x64 tile, BK=16, 128 threads, 8x4 microtile
// (32 FFMA + 3 LDS.128 per k-step). Per-element k-order identical to the
// 4x4 version -> bit-identical results. Mirror epilogues as before.
// ---------------------------------------------------------------------------
template<int MIR>
__global__ __launch_bounds__(128)
void k_sgemm(const float* __restrict__ A, int lda, long long sA,
             const float* __restrict__ B, int ldb, long long sB,
             float* __restrict__ C, int ldc, long long sC,
             int M, int N, int K, float alpha)
{
    __shared__ __align__(16) float As[2][16][68];
    __shared__ __align__(16) float Bs[2][16][68];
    int b = blockIdx.z;
    A += (long long)b * sA;
    B += (long long)b * sB;
    C += (long long)b * sC;
    int tid = threadIdx.x;
    int m0 = blockIdx.y * 64, n0 = blockIdx.x * 64;
    int mt = (tid & 7) * 8;
    int nt = (tid >> 3) * 4;
    int ra_r[8], ra_c[8], rb_r[8], rb_c[8];
#pragma unroll
    for (int e = 0; e < 8; e++) {
        int idx = tid + e * 128;
        ra_r[e] = idx >> 4; ra_c[e] = idx & 15;
        rb_r[e] = idx >> 6; rb_c[e] = idx & 63;
    }
    float ra[8], rb[8];
    int ntiles = (K + 15) / 16;

#pragma unroll
    for (int e = 0; e < 8; e++) {
        int gm = m0 + ra_r[e], gk = ra_c[e];
        ra[e] = (gm < M && gk < K) ? A[(long long)gm * lda + gk] : 0.f;
        int gk2 = rb_r[e], gn = n0 + rb_c[e];
        rb[e] = (gk2 < K && gn < N) ? B[(long long)gk2 * ldb + gn] : 0.f;
    }
#pragma unroll
    for (int e = 0; e < 8; e++) {
        As[0][ra_c[e]][ra_r[e]] = ra[e];
        Bs[0][rb_r[e]][rb_c[e]] = rb[e];
    }
    __syncthreads();

    float acc[8][4] = {};
    for (int t = 0; t < ntiles; t++) {
        int kt = (t + 1) * 16;
        if (t + 1 < ntiles) {
#pragma unroll
            for (int e = 0; e < 8; e++) {
                int gm = m0 + ra_r[e], gk = kt + ra_c[e];
                ra[e] = (gm < M && gk < K) ? A[(long long)gm * lda + gk] : 0.f;
                int gk2 = kt + rb_r[e], gn = n0 + rb_c[e];
                rb[e] = (gk2 < K && gn < N) ? B[(long long)gk2 * ldb + gn] : 0.f;
            }
        }
        int cur = t & 1;
#pragma unroll
        for (int k = 0; k < 16; k++) {
            float av[8], bv[4];
            *(float4*)&av[0] = *(const float4*)&As[cur][k][mt];
            *(float4*)&av[4] = *(const float4*)&As[cur][k][mt + 4];
            *(float4*)&bv[0] = *(const float4*)&Bs[cur][k][nt];
#pragma unroll
            for (int i = 0; i < 8; i++)
#pragma unroll
                for (int j = 0; j < 4; j++)
                    acc[i][j] = fmaf(av[i], bv[j], acc[i][j]);
        }
        if (t + 1 < ntiles) {
            int nxt = cur ^ 1;
#pragma unroll
            for (int e = 0; e < 8; e++) {
                As[nxt][ra_c[e]][ra_r[e]] = ra[e];
                Bs[nxt][rb_r[e]][rb_c[e]] = rb[e];
            }
        }
        __syncthreads();
    }

#pragma unroll
    for (int i = 0; i < 8; i++) {
        int gm = m0 + mt + i;
        if (gm >= M) continue;
#pragma unroll
        for (int j = 0; j < 4; j++) {
            int gn = n0 + nt + j;
            if (gn >= N) continue;
            float v = alpha * acc[i][j];
            if (MIR == 0) {
                C[(long long)gm * ldc + gn] = v;
            } else if (MIR == 1) {
                C[(long long)gm * ldc + 256 + gn] = v;
                if (gn > 0) C[(long long)gm * ldc + 256 - gn] = -v;
            } else {
                C[(long long)(256 + gm) * ldc + gn] = v;
                if (gm > 0) C[(long long)(256 - gm) * ldc + gn] = -v;
            }
        }
    }
}

// ---------------------------------------------------------------------------
// Combined corner fold: cD -> Af = [A1f ; A2f] (516 x 516).
// ---------------------------------------------------------------------------
__global__ void k_foldA(const float2* __restrict__ cD, float* __restrict__ Af)
{
    int b = blockIdx.z;
    int kc = blockIdx.x * 32 + threadIdx.x;
    int kr = blockIdx.y * 8 + threadIdx.y;
    if (kc >= NK || kr >= NK) return;
    const float2* D = cD + (long long)b * NN;
    bool pc = (kc >= 1 && kc <= 255);
    bool pr = (kr >= 1 && kr <= 255);
    float2 z = make_float2(0.f, 0.f);
    float2 pp = D[(long long)(255 + kr) * NG + 255 + kc];
    float2 pm = pc ? D[(long long)(255 + kr) * NG + 255 - kc] : z;
    float2 mp = pr ? D[(long long)(255 - kr) * NG + 255 + kc] : z;
    float2 mm = (pc && pr) ? D[(long long)(255 - kr) * NG + 255 - kc] : z;
    float* a1 = Af + (long long)b * NAF + (long long)kr * NK2;
    float* a2 = Af + (long long)b * NAF + (long long)(NK + kr) * NK2;
    a1[kc]      = (pp.x + pm.x) + (mp.x + mm.x);
    a1[NK + kc] = -((pp.y - pm.y) + (mp.y - mm.y));
    a2[kc]      = (pp.y + pm.y) - (mp.y + mm.y);
    a2[NK + kc] = (pp.x - pm.x) - (mp.x - mm.x);
}

// ---------------------------------------------------------------------------
// wt*ik2 helper
// ---------------------------------------------------------------------------
DINLINE float2 wtik_apply(float2 c, float wrv, float wiv, int p, int q)
{
    float dp = (float)(p - 256), dq = (float)(q - 256);
    float s = dp * dp + dq * dq;
    const float pi2 = 9.869604401089358f;
    float ik = (s == 0.f) ? 1.f : 1.f / (pi2 * s);
    float2 rr;
    rr.x = (c.x * wrv - c.y * wiv) * ik;
    rr.y = (c.x * wiv + c.y * wrv) * ik;
    return rr;
}

// ---------------------------------------------------------------------------
// Composed 7x7 forward conv (real input) + wt*ik2. 2 px/thread.
// ---------------------------------------------------------------------------
__global__ __launch_bounds__(256)
void k_conv7f(const float* __restrict__ X, float2* __restrict__ Y,
              const float2* __restrict__ wf,
              const float* __restrict__ wtr, const float* __restrict__ wti)
{
    int b = blockIdx.z;
    __shared__ float2 ws[49];
    int t = threadIdx.y * 16 + threadIdx.x;
    if (t < 49) ws[t] = wf[b * 49 + t];
    __syncthreads();
    int q = blockIdx.x * 16 + threadIdx.x;
    int p0 = blockIdx.y * 32 + 2 * threadIdx.y;
    if (q >= NG || p0 >= NG) return;
    bool hasP1 = (p0 + 1 < NG);
    const float* Xb = X + (long long)b * NN;
    float2 a0 = make_float2(0.f, 0.f), a1 = make_float2(0.f, 0.f);
    int pB = blockIdx.y * 32, qB = blockIdx.x * 16;
    bool interior = (pB >= 3) && (pB + 34 <= NG - 1) && (qB >= 3) && (qB + 18 <= NG - 1);
    if (interior) {
#pragma unroll
        for (int r = 0; r < 8; r++) {
            int row = p0 - 3 + r;
            float xr[7];
#pragma unroll
            for (int c = 0; c < 7; c++) xr[c] = Xb[(long long)row * NG + q - 3 + c];
#pragma unroll
            for (int dx = 0; dx < 7; dx++) {
                if (r < 7) {
                    float2 w = ws[r * 7 + dx];
                    a0.x = fmaf(xr[dx], w.x, a0.x);
                    a0.y = fmaf(xr[dx], w.y, a0.y);
                }
                if (r >= 1) {
                    float2 w = ws[(r - 1) * 7 + dx];
                    a1.x = fmaf(xr[dx], w.x, a1.x);
                    a1.y = fmaf(xr[dx], w.y, a1.y);
                }
            }
        }
    } else {
#pragma unroll
        for (int r = 0; r < 8; r++) {
            int row = p0 - 3 + r;
            bool vr = (row >= 0 && row < NG);
            float xr[7];
#pragma unroll
            for (int c = 0; c < 7; c++) {
                int col = q - 3 + c;
                xr[c] = (vr && col >= 0 && col < NG) ? Xb[(long long)row * NG + col] : 0.f;
            }
#pragma unroll
            for (int dx = 0; dx < 7; dx++) {
                if (r < 7) {
                    float2 w = ws[r * 7 + dx];
                    a0.x = fmaf(xr[dx], w.x, a0.x);
                    a0.y = fmaf(xr[dx], w.y, a0.y);
                }
                if (r >= 1) {
                    float2 w = ws[(r - 1) * 7 + dx];
                    a1.x = fmaf(xr[dx], w.x, a1.x);
                    a1.y = fmaf(xr[dx], w.y, a1.y);
                }
            }
        }
    }
    float2* Yb = Y + (long long)b * NN;
    {
        long long o = (long long)b * NN + (long long)p0 * NG + q;
        Yb[(long long)p0 * NG + q] = wtik_apply(a0, wtr[o], wti[o], p0, q);
    }
    if (hasP1) {
        long long o = (long long)b * NN + (long long)(p0 + 1) * NG + q;
        Yb[(long long)(p0 + 1) * NG + q] = wtik_apply(a1, wtr[o], wti[o], p0 + 1, q);
    }
}

// ---------------------------------------------------------------------------
// Composed 7x7 backward conv (complex input), taps = conj(wf^T). 2 px/thread.
// ---------------------------------------------------------------------------
__global__ __launch_bounds__(256)
void k_conv7b(const float2* __restrict__ X, float2* __restrict__ Y,
              const float2* __restrict__ wf)
{
    int b = blockIdx.z;
    __shared__ float2 ws[49];
    int t = threadIdx.y * 16 + threadIdx.x;
    if (t < 49) {
        int dy = t / 7, dx = t % 7;
        float2 v = wf[b * 49 + dx * 7 + dy];
        ws[t] = make_float2(v.x, -v.y);
    }
    __syncthreads();
    int q = blockIdx.x * 16 + threadIdx.x;
    int p0 = blockIdx.y * 32 + 2 * threadIdx.y;
    if (q >= NG || p0 >= NG) return;
    bool hasP1 = (p0 + 1 < NG);
    const float2* Xb = X + (long long)b * NN;
    float2 a0 = make_float2(0.f, 0.f), a1 = make_float2(0.f, 0.f);
    int pB = blockIdx.y * 32, qB = blockIdx.x * 16;
    bool interior = (pB >= 3) && (pB + 34 <= NG - 1) && (qB >= 3) && (qB + 18 <= NG - 1);
    if (interior) {
#pragma unroll
        for (int r = 0; r < 8; r++) {
            int row = p0 - 3 + r;
            float2 xr[7];
#pragma unroll
            for (int c = 0; c < 7; c++) xr[c] = Xb[(long long)row * NG + q - 3 + c];
#pragma unroll
            for (int dx = 0; dx < 7; dx++) {
                if (r < 7) a0 = cmad(a0, xr[dx], ws[r * 7 + dx]);
                if (r >= 1) a1 = cmad(a1, xr[dx], ws[(r - 1) * 7 + dx]);
            }
        }
    } else {
#pragma unroll
        for (int r = 0; r < 8; r++) {
            int row = p0 - 3 + r;
            bool vr = (row >= 0 && row < NG);
            float2 xr[7];
#pragma unroll
            for (int c = 0; c < 7; c++) {
                int col = q - 3 + c;
                xr[c] = (vr && col >= 0 && col < NG)
                      ? Xb[(long long)row * NG + col] : make_float2(0.f, 0.f);
            }
#pragma unroll
            for (int dx = 0; dx < 7; dx++) {
                if (r < 7) a0 = cmad(a0, xr[dx], ws[r * 7 + dx]);
                if (r >= 1) a1 = cmad(a1, xr[dx], ws[(r - 1) * 7 + dx]);
            }
        }
    }
    float2* Yb = Y + (long long)b * NN;
    Yb[(long long)p0 * NG + q] = a0;
    if (hasP1) Yb[(long long)(p0 + 1) * NG + q] = a1;
}

// ---------------------------------------------------------------------------
// Strip conv: exact sequential 3x3 conv on a boundary frame of width FW.
// ---------------------------------------------------------------------------
template<int CO, int CI, int FW, bool REAL_IN, bool WTIK>
__global__ __launch_bounds__(256)
void k_conv_strip(const void* __restrict__ Xv, float2* __restrict__ Y,
                  const float* __restrict__ wr, const float* __restrict__ wi,
                  int conjt, const float* __restrict__ wtr,
                  const float* __restrict__ wti)
{
    int b = blockIdx.y;
    __shared__ float2 ws[CO * CI * 9];
    int t = threadIdx.x;
    if (t < CO * CI * 9) {
        int o = t / (CI * 9), rem = t % (CI * 9), i = rem / 9, tap = rem % 9;
        int dy = tap / 3, dx = tap % 3;
        long long widx;
        float sgn;
        if (conjt) { widx = ((long long)(b * CI + i) * CO + o) * 9 + dx * 3 + dy; sgn = -1.f; }
        else       { widx = ((long long)(b * CO + o) * CI + i) * 9 + dy * 3 + dx; sgn =  1.f; }
        ws[t] = make_float2(wr[widx], sgn * wi[widx]);
    }
    __syncthreads();

    const int nTop = FW * NG;
    const int nSide = (NG - 2 * FW) * FW;
    const int total = 2 * nTop + 2 * nSide;
    int idx = blockIdx.x * 256 + t;
    if (idx >= total) return;
    int p, q;
    if (idx < nTop)            { p = idx / NG; q = idx - p * NG; }
    else if (idx < 2 * nTop)   { int k2 = idx - nTop; p = NG - FW + k2 / NG; q = k2 % NG; }
    else if (idx < 2 * nTop + nSide) { int k2 = idx - 2 * nTop; p = FW + k2 / FW; q = k2 % FW; }
    else                       { int k2 = idx - 2 * nTop - nSide; p = FW + k2 / FW; q = NG - FW + k2 % FW; }

    float2 acc[CO];
#pragma unroll
    for (int o = 0; o < CO; o++) acc[o] = make_float2(0.f, 0.f);
#pragma unroll
    for (int i = 0; i < CI; i++) {
#pragma unroll
        for (int dy = 0; dy < 3; dy++) {
            int ii = p + dy - 1;
#pragma unroll
            for (int dx = 0; dx < 3; dx++) {
                int jj = q + dx - 1;
                float2 xv = make_float2(0.f, 0.f);
                if (ii >= 0 && ii < NG && jj >= 0 && jj < NG) {
                    if (REAL_IN) {
                        const float* Xb = (const float*)Xv + (long long)b * NN;
                        xv.x = Xb[(long long)ii * NG + jj];
                    } else {
                        const float2* Xb = (const float2*)Xv + (long long)b * CI * NN;
                        xv = Xb[(long long)i * NN + (long long)ii * NG + jj];
                    }
                }
                int tap = dy * 3 + dx;
#pragma unroll
                for (int o = 0; o < CO; o++)
                    acc[o] = cmad(acc[o], xv, ws[(o * CI + i) * 9 + tap]);
            }
        }
    }
    float2* Yb = Y + (long long)b * CO * NN;
    long long po = (long long)p * NG + q;
    if (WTIK) {
        long long o = (long long)b * NN + po;
        Yb[po] = wtik_apply(acc[0], wtr[o], wti[o], p, q);
    } else {
#pragma unroll
        for (int o = 0; o < CO; o++) Yb[(long long)o * NN + po] = acc[o];
    }
}

// ---------------------------------------------------------------------------
// Reductions (deterministic, double accumulation)
// ---------------------------------------------------------------------------
__global__ __launch_bounds__(256)
void k_alpha_part(const float* __restrict__ r, const float* __restrict__ e,
                  const float* __restrict__ a, double* __restrict__ p1,
                  double* __restrict__ p2)
{
    int b = blockIdx.y;
    const float* rb = r + (long long)b * NN;
    const float* eb = e + (long long)b * NN;
    const float* ab = a + (long long)b * NCC;
    double num = 0.0, den = 0.0;
    for (long long idx = (long long)blockIdx.x * 256 + threadIdx.x; idx < NN;
         idx += (long long)gridDim.x * 256) {
        int i = (int)(idx / NG), j = (int)(idx - (long long)i * NG);
        float ev = eb[idx];
        num += (double)(rb[idx] * ev);
        if (i > 0 && j > 0 && i < NG - 1 && j < NG - 1) {
            float d = darcy_at(eb, ab, i, j);
            den += (double)(d * ev);
        }
    }
    __shared__ double s1[256], s2[256];
    int t = threadIdx.x;
    s1[t] = num; s2[t] = den;
    __syncthreads();
    for (int s = 128; s > 0; s >>= 1) {
        if (t < s) { s1[t] += s1[t + s]; s2[t] += s2[t + s]; }
        __syncthreads();
    }
    if (t == 0) { p1[b * NBLK_A + blockIdx.x] = s1[0]; p2[b * NBLK_A + blockIdx.x] = s2[0]; }
}

__global__ void k_alpha_fin(const double* __restrict__ p1,
                            const double* __restrict__ p2,
                            float* __restrict__ alpha)
{
    int b = blockIdx.x;
    __shared__ double s1[256], s2[256];
    double n = 0.0, d = 0.0;
    for (int i = threadIdx.x; i < NBLK_A; i += 256) {
        n += p1[b * NBLK_A + i]; d += p2[b * NBLK_A + i];
    }
    int t = threadIdx.x;
    s1[t] = n; s2[t] = d;
    __syncthreads();
    for (int s = 128; s > 0; s >>= 1) {
        if (t < s) { s1[t] += s1[t + s]; s2[t] += s2[t + s]; }
        __syncthreads();
    }
    if (t == 0) alpha[b] = (float)(s1[0] / s2[0]);
}

__global__ void k_update(float* __restrict__ x, const float* __restrict__ e,
                         const float* __restrict__ alpha)
{
    int b = blockIdx.z;
    int j = blockIdx.x * 16 + threadIdx.x + 1;
    int i = blockIdx.y * 16 + threadIdx.y + 1;
    if (i > NI || j > NI) return;
    long long o = (long long)b * NN + (long long)i * NG + j;
    x[o] = fmaf(alpha[b], e[o], x[o]);
}

__global__ __launch_bounds__(256)
void k_norm_part(const float* __restrict__ r, const float* __restrict__ f,
                 double* __restrict__ p1, double* __restrict__ p2)
{
    double sr = 0.0, sf = 0.0;
    long long tot = (long long)NB * NN;
    for (long long idx = (long long)blockIdx.x * 256 + threadIdx.x; idx < tot;
         idx += (long long)gridDim.x * 256) {
        float rv = r[idx], fv = f[idx];
        sr += (double)rv * rv;
        sf += (double)fv * fv;
    }
    __shared__ double s1[256], s2[256];
    int t = threadIdx.x;
    s1[t] = sr; s2[t] = sf;
    __syncthreads();
    for (int s = 128; s > 0; s >>= 1) {
        if (t < s) { s1[t] += s1[t + s]; s2[t] += s2[t + s]; }
        __syncthreads();
    }
    if (t == 0) { p1[blockIdx.x] = s1[0]; p2[blockIdx.x] = s2[0]; }
}

__global__ void k_norm_fin(const double* __restrict__ p1,
                           const double* __restrict__ p2,
                           float* __restrict__ out)
{
    __shared__ double s1[256], s2[256];
    double a = 0.0, b = 0.0;
    for (int i = threadIdx.x; i < NBLK_N; i += 256) { a += p1[i]; b += p2[i]; }
    int t = threadIdx.x;
    s1[t] = a; s2[t] = b;
    __syncthreads();
    for (int s = 128; s > 0; s >>= 1) {
        if (t < s) { s1[t] += s1[t + s]; s2[t] += s2[t + s]; }
        __syncthreads();
    }
    if (t == 0) out[0] = (float)sqrt(s1[0] / s2[0]);
}

// ---------------------------------------------------------------------------
// Host orchestration
// ---------------------------------------------------------------------------
template<typename T>
static T* sym_addr(const void* sym)
{
    void* p = nullptr;
    cudaGetSymbolAddress(&p, sym);
    return (T*)p;
}

static inline int strip_blocks(int FW)
{
    int nTop = FW * NG, nSide = (NG - 2 * FW) * FW;
    int total = 2 * nTop + 2 * nSide;
    return (total + 255) / 256;
}

extern "C" void kernel_launch(void* const* d_in, const int* in_sizes, int n_in,
                              void* d_out, int out_size)
{
    const float* f    = (const float*)d_in[0];
    const float* coef = (const float*)d_in[1];
    const float* w1r = (const float*)d_in[3];
    const float* w1i = (const float*)d_in[4];
    const float* w2r = (const float*)d_in[5];
    const float* w2i = (const float*)d_in[6];
    const float* w3r = (const float*)d_in[7];
    const float* w3i = (const float*)d_in[8];
    const float* wtr = (const float*)d_in[9];
    const float* wti = (const float*)d_in[10];

    float*  x    = sym_addr<float>(g_x);
    float*  x2   = sym_addr<float>(g_x2);
    float*  r    = sym_addr<float>(g_r);
    float*  e    = sym_addr<float>(g_e);
    float*  rh   = sym_addr<float>(g_rh);
    float*  dinv = sym_addr<float>(g_dinv);
    float*  S    = sym_addr<float>(g_S);
    float*  St   = sym_addr<float>(g_St);
    float*  U    = sym_addr<float>(g_U);
    float2* cA   = sym_addr<float2>(g_cA);
    float2* cB   = sym_addr<float2>(g_cB);
    float2* cC   = sym_addr<float2>(g_cC);
    float2* cD   = sym_addr<float2>(g_cD);
    float2* wf   = sym_addr<float2>(g_wf);
    float*  Af   = sym_addr<float>(g_Af);
    float*  F    = sym_addr<float>(g_F);
    float*  Bm   = sym_addr<float>(g_Bm);
    float*  Em   = sym_addr<float>(g_Em);
    double* pd1  = sym_addr<double>(g_pd1);
    double* pd2  = sym_addr<double>(g_pd2);
    float*  alph = sym_addr<float>(g_alpha);

    dim3 blk2(16, 16);
    dim3 gInt((NI + 15) / 16, (NI + 15) / 16, NB);
    dim3 gFull((NG + 15) / 16, (NG + 15) / 16, NB);
    dim3 gConv((NG + 15) / 16, (NG + 31) / 32, NB);
    dim3 gJac((NG + 31) / 32, (NG + 31) / 32, NB);

    dim3 gS5(strip_blocks(5), NB);
    dim3 gS4(strip_blocks(4), NB);
    dim3 gS3(strip_blocks(3), NB);

    dim3 blkF(32, 8);
    dim3 gFo((NK + 31) / 32, (NK + 7) / 8, NB);

    // ---- setup (1 segmented kernel + conv composition) ----
    {
        long long total = (long long)NB * NN + (long long)NG * NI
                        + (long long)NK2 * NI + (long long)NI * NK2
                        + (long long)NB * NII;
        k_setup<<<(int)((total + 255) / 256), 256>>>(x, x2, e, S, St, Bm, Em,
                                                     coef, dinv);
        k_compose<<<NB, 64>>>(w1r, w1i, w2r, w2i, w3r, w3i, wf);
    }

    for (int step = 0; step < KSTEPS; step++) {
        // ---- 10 Jacobi sweeps (2 fused kernels) + residual ----
        k_jacobi5<false><<<gJac, 256>>>(x, x2, f, coef, dinv, nullptr);
        k_jacobi5<true ><<<gJac, 256>>>(x2, x, f, coef, dinv, r);

        // ---- forward sine transform (odd symmetry fused in epilogue) ----
        {
            dim3 g((257 + 63) / 64, (NI + 63) / 64, NB);
            k_sgemm<1><<<g, 128>>>(r + NG + 1, NG, NN,
                                   St + 256, NG, 0,
                                   U, NG, NIG,
                                   NI, 257, NI, 1.f);
        }
        {
            dim3 g((NG + 63) / 64, (257 + 63) / 64, NB);
            k_sgemm<2><<<g, 128>>>(S + 256 * NI, NI, 0,
                                   U, NG, NIG,
                                   rh, NG, NN,
                                   257, NG, NI, -1.f / (512.f * 512.f));
        }

        // ---- forward conv chain: composed 7x7 + exact ring correction ----
        k_conv7f<<<gConv, blk2>>>(rh, cC, wf, wtr, wti);
        k_conv_strip<4, 1, 5, true,  false><<<gS5, 256>>>(rh, cA, w1r, w1i, 0, nullptr, nullptr);
        k_conv_strip<4, 4, 4, false, false><<<gS4, 256>>>(cA, cB, w2r, w2i, 0, nullptr, nullptr);
        k_conv_strip<1, 4, 3, false, true ><<<gS3, 256>>>(cB, cC, w3r, w3i, 0, wtr, wti);

        // ---- backward conv chain: composed conj(wf^T) + ring correction ----
        k_conv7b<<<gConv, blk2>>>(cC, cD, wf);
        k_conv_strip<4, 1, 5, false, false><<<gS5, 256>>>(cC, cA, w3r, w3i, 1, nullptr, nullptr);
        k_conv_strip<4, 4, 4, false, false><<<gS4, 256>>>(cA, cB, w2r, w2i, 1, nullptr, nullptr);
        k_conv_strip<1, 4, 3, false, false><<<gS3, 256>>>(cB, cD, w1r, w1i, 1, nullptr, nullptr);

        // ---- inverse transform: corner-fold then 2 real GEMMs ----
        k_foldA<<<gFo, blkF>>>(cD, Af);
        {
            dim3 g((NI + 63) / 64, (NK2 + 63) / 64, NB);
            k_sgemm<0><<<g, 128>>>(Af, NK2, NAF, Bm, NI, 0, F, NI, NF,
                                   NK2, NI, NK2, 1.f);
        }
        {
            dim3 g((NI + 63) / 64, (NI + 63) / 64, NB);
            k_sgemm<0><<<g, 128>>>(Em, NK2, 0, F, NI, NF, e + NG + 1, NG, NN,
                                   NI, NI, NK2, 1.f);
        }

        // ---- alpha and update ----
        {
            dim3 g(NBLK_A, NB);
            k_alpha_part<<<g, 256>>>(r, e, coef, pd1, pd2);
            k_alpha_fin<<<NB, 256>>>(pd1, pd2, alph);
            k_update<<<gInt, blk2>>>(x, e, alph);
        }
    }

    // ---- final relative residual norm ----
    k_resid<<<gFull, blk2>>>(x, f, coef, r);
    k_norm_part<<<NBLK_N, 256>>>(r, f, pd1, pd2);
    k_norm_fin<<<1, 256>>>(pd1, pd2, (float*)d_out);
}

// round 15
// speedup vs baseline: 1.1139x; 1.1139x over previous
#include <cuda_runtime.h>
#include <math.h>

#define DINLINE __device__ __forceinline__

// ---------------------------------------------------------------------------
// Fixed problem dimensions (B=4, grid 513, coef 512, epoch=101 -> K=2)
// ---------------------------------------------------------------------------
namespace fns {
constexpr int NB = 4;
constexpr int NG = 513;
constexpr int NI = 511;
constexpr int NC = 512;
constexpr int NK = 258;
constexpr int NK2 = 516;
constexpr long long NN  = (long long)NG * NG;
constexpr long long NCC = (long long)NC * NC;
constexpr long long NII = (long long)NI * NI;
constexpr long long NIG = (long long)NI * NG;
constexpr long long NAF = (long long)NK2 * NK2;  // folded A: 516 x 516
constexpr long long NF  = (long long)NK2 * NI;   // 516 x 511
constexpr int NBLK_A = 128;
constexpr int NBLK_N = 256;
constexpr int KSTEPS = 2;
}
using namespace fns;

// ---------------------------------------------------------------------------
// Static device scratch
// ---------------------------------------------------------------------------
__device__ float  g_x   [NB * NN];
__device__ float  g_x2  [NB * NN];
__device__ float  g_r   [NB * NN];
__device__ float  g_e   [NB * NN];
__device__ float  g_rh  [NB * NN];
__device__ float  g_dinv[NB * NII];
__device__ float  g_S   [NG * (long long)NI];  // S[p][j], ld=NI
__device__ float  g_St  [NIG];                 // St[j][p], ld=NG
__device__ float  g_U   [NB * NIG];            // 511 x 513, ld=NG
__device__ float2 g_cA  [NB * 4 * NN];         // strip scratch stage-1
__device__ float2 g_cB  [NB * 4 * NN];         // strip scratch stage-2
__device__ float2 g_cC  [NB * NN];             // spectral signal
__device__ float2 g_cD  [NB * NN];             // backward-conv output
__device__ float2 g_wf  [NB * 49];             // composed 7x7 forward taps
__device__ float  g_Af  [NB * NAF];            // folded [A1f ; A2f], 516 x 516
__device__ float  g_F   [NB * NF];             // [A ; B], 516 x 511
__device__ float  g_Bm  [NF];                  // [C ; S], 516 x 511 (const)
__device__ float  g_Em  [(long long)NI * NK2]; // [Cos | Sin], 511 x 516 (const)
__device__ double g_pd1 [2048];
__device__ double g_pd2 [2048];
__device__ float  g_alpha[NB];

// ---------------------------------------------------------------------------
// Darcy FEM 9-point stencil (global-memory form, for resid / alpha)
// ---------------------------------------------------------------------------
DINLINE float darcy_at(const float* __restrict__ x,
                       const float* __restrict__ a, int i, int j)
{
    const float c23 = 2.f / 3.f, c16 = -1.f / 6.f, c13 = -1.f / 3.f;
    float s = 0.f;
#pragma unroll
    for (int u = 0; u < 2; u++) {
#pragma unroll
        for (int v = 0; v < 2; v++) {
            int I = i - 1 + u, J = j - 1 + v;
            float av = a[(long long)I * NC + J];
            float k0, k1, k2, k3;
            if (u == 0 && v == 0) { k0 = c16; k1 = c23; k2 = c16; k3 = c13; }
            else if (u == 0 && v == 1) { k0 = c23; k1 = c16; k2 = c13; k3 = c16; }
            else if (u == 1 && v == 0) { k0 = c13; k1 = c16; k2 = c23; k3 = c16; }
            else                        { k0 = c16; k1 = c13; k2 = c16; k3 = c23; }
            s += av * (k3 * x[(long long)I * NG + J]
                     + k2 * x[(long long)I * NG + J + 1]
                     + k0 * x[(long long)(I + 1) * NG + J]
                     + k1 * x[(long long)(I + 1) * NG + J + 1]);
        }
    }
    return s;
}

DINLINE float2 cmad(float2 acc, float2 a, float2 b)
{
    acc.x = fmaf(a.x, b.x, fmaf(-a.y, b.y, acc.x));
    acc.y = fmaf(a.x, b.y, fmaf(a.y, b.x, acc.y));
    return acc;
}

// ---------------------------------------------------------------------------
// One segmented setup kernel: zero x/x2/e, S/St, Bm, Em, dinv
// ---------------------------------------------------------------------------
__global__ void k_setup(float* __restrict__ x, float* __restrict__ x2,
                        float* __restrict__ e,
                        float* __restrict__ S, float* __restrict__ St,
                        float* __restrict__ Bm, float* __restrict__ Em,
                        const float* __restrict__ a, float* __restrict__ dinv)
{
    long long idx = (long long)blockIdx.x * blockDim.x + threadIdx.x;
    const long long T0 = (long long)NB * NN;
    const long long T1 = T0 + (long long)NG * NI;
    const long long T2 = T1 + (long long)NK2 * NI;
    const long long T3 = T2 + (long long)NI * NK2;
    const long long T4 = T3 + (long long)NB * NII;
    if (idx < T0) {
        x[idx] = 0.f; x2[idx] = 0.f; e[idx] = 0.f;
    } else if (idx < T1) {
        long long t = idx - T0;
        int p = (int)(t / NI), j = (int)(t - (long long)p * NI);
        int m = (j + 1) * (p - 256);
        int mm = ((m % 1024) + 1024) % 1024;
        float v = sinpif((float)mm / 512.f);
        S[t] = v;
        St[(long long)j * NG + p] = v;
    } else if (idx < T2) {
        long long t = idx - T1;
        int k2 = (int)(t / NI), s = (int)(t - (long long)k2 * NI);
        int k = (k2 < NK) ? k2 : k2 - NK;
        int tm = (2 * k * s) % 2050;
        float xr = (float)tm / 1025.f;
        Bm[t] = (k2 < NK) ? cospif(xr) : -sinpif(xr);
    } else if (idx < T3) {
        long long t = idx - T2;
        int s = (int)(t / NK2), k2 = (int)(t - (long long)s * NK2);
        int k = (k2 < NK) ? k2 : k2 - NK;
        int tm = (2 * s * k) % 2050;
        float xr = (float)tm / 1025.f;
        Em[t] = (k2 < NK) ? cospif(xr) : sinpif(xr);
    } else if (idx < T4) {
        long long t = idx - T3;
        int b = (int)(t / NII);
        long long rem = t - (long long)b * NII;
        int p = (int)(rem / NI), q = (int)(rem - (long long)p * NI);
        const float* ap = a + (long long)b * NCC;
        float s = ap[(long long)p * NC + q] + ap[(long long)p * NC + q + 1]
                + ap[(long long)(p + 1) * NC + q] + ap[(long long)(p + 1) * NC + q + 1];
        dinv[t] = 1.f / ((2.f / 3.f) * s);
    }
}

// ---------------------------------------------------------------------------
// Compose the 3-stage complex conv chain into one 7x7 tap set.
// ---------------------------------------------------------------------------
__global__ void k_compose(const float* __restrict__ w1r, const float* __restrict__ w1i,
                          const float* __restrict__ w2r, const float* __restrict__ w2i,
                          const float* __restrict__ w3r, const float* __restrict__ w3i,
                          float2* __restrict__ wf)
{
    int b = blockIdx.x;
    int t = threadIdx.x;
    if (t >= 49) return;
    int dy = t / 7, dx = t % 7;
    float accr = 0.f, acci = 0.f;
    for (int c = 0; c < 4; c++) {
        for (int o = 0; o < 4; o++) {
            for (int a = 0; a < 9; a++) {
                int ay = a / 3, ax = a % 3;
                float r1 = w1r[(b * 4 + c) * 9 + a];
                float i1 = w1i[(b * 4 + c) * 9 + a];
                for (int bt = 0; bt < 9; bt++) {
                    int by = bt / 3, bx = bt % 3;
                    int cy = dy - ay - by, cx = dx - ax - bx;
                    if (cy < 0 || cy > 2 || cx < 0 || cx > 2) continue;
                    float r2 = w2r[((b * 4 + o) * 4 + c) * 9 + bt];
                    float i2 = w2i[((b * 4 + o) * 4 + c) * 9 + bt];
                    float r3 = w3r[(b * 4 + o) * 9 + cy * 3 + cx];
                    float i3 = w3i[(b * 4 + o) * 9 + cy * 3 + cx];
                    float tr = r1 * r2 - i1 * i2;
                    float ti = r1 * i2 + i1 * r2;
                    accr += tr * r3 - ti * i3;
                    acci += tr * i3 + ti * r3;
                }
            }
        }
    }
    wf[b * 49 + t] = make_float2(accr, acci);
}

// ---------------------------------------------------------------------------
// Fused Jacobi: 5 sweeps in one kernel via smem (44x44 tile, halo 6).
// Boundary encoded in ds (0.75*dinv, 0 on boundary): fmaf(0, rr, old) = old,
// so the per-cell interior branch is gone (bit-identical). RESID variant
// also writes r = f - A(x_final) for its 32x32 output tile.
// ---------------------------------------------------------------------------
template<bool RESID>
__global__ __launch_bounds__(256)
void k_jacobi5(const float* __restrict__ xin, float* __restrict__ xout,
               const float* __restrict__ f, const float* __restrict__ a,
               const float* __restrict__ dinv, float* __restrict__ rout)
{
    constexpr int W = 44, HALO = 6, SW = 5;
    __shared__ float xs[2][W][W];
    __shared__ float as[W][W], fs[W][W], ds[W][W];
    int b = blockIdx.z;
    int Oi = blockIdx.y * 32, Oj = blockIdx.x * 32;
    const float* xp = xin + (long long)b * NN;
    const float* fp = f + (long long)b * NN;
    const float* ap = a + (long long)b * NCC;
    const float* dp = dinv + (long long)b * NII;
    float* xo = xout + (long long)b * NN;
    int tid = threadIdx.x;

    for (int idx = tid; idx < W * W; idx += 256) {
        int li = idx / W, lj = idx - (idx / W) * W;
        int gi = Oi - HALO + li, gj = Oj - HALO + lj;
        bool inx = (gi >= 0 && gi <= 512 && gj >= 0 && gj <= 512);
        xs[0][li][lj] = inx ? xp[(long long)gi * NG + gj] : 0.f;
        fs[li][lj]    = inx ? fp[(long long)gi * NG + gj] : 0.f;
        bool ina = (gi >= 0 && gi <= 511 && gj >= 0 && gj <= 511);
        as[li][lj] = ina ? ap[(long long)gi * NC + gj] : 0.f;
        bool ind = (gi >= 1 && gi <= 511 && gj >= 1 && gj <= 511);
        ds[li][lj] = ind ? 0.75f * dp[(long long)(gi - 1) * NI + (gj - 1)] : 0.f;
    }
    __syncthreads();

    const float c23 = 2.f / 3.f, c16 = -1.f / 6.f, c13 = -1.f / 3.f;
    int cur = 0;
    for (int s = 1; s <= SW; s++) {
        for (int idx = tid; idx < W * W; idx += 256) {
            int li = idx / W, lj = idx - (idx / W) * W;
            if (li < s || li >= W - s || lj < s || lj >= W - s) continue;
            float old = xs[cur][li][lj];
            float sum = 0.f;
#pragma unroll
            for (int u = 0; u < 2; u++) {
#pragma unroll
                for (int v = 0; v < 2; v++) {
                    float av = as[li - 1 + u][lj - 1 + v];
                    float k0, k1, k2, k3;
                    if (u == 0 && v == 0) { k0 = c16; k1 = c23; k2 = c16; k3 = c13; }
                    else if (u == 0 && v == 1) { k0 = c23; k1 = c16; k2 = c13; k3 = c16; }
                    else if (u == 1 && v == 0) { k0 = c13; k1 = c16; k2 = c23; k3 = c16; }
                    else                        { k0 = c16; k1 = c13; k2 = c16; k3 = c23; }
                    sum += av * (k3 * xs[cur][li - 1 + u][lj - 1 + v]
                               + k2 * xs[cur][li - 1 + u][lj + v]
                               + k0 * xs[cur][li + u][lj - 1 + v]
                               + k1 * xs[cur][li + u][lj + v]);
                }
            }
            // ds==0 on boundary -> value stays exactly `old` (bit-identical)
            xs[cur ^ 1][li][lj] = fmaf(ds[li][lj], fs[li][lj] - sum, old);
        }
        __syncthreads();
        cur ^= 1;
    }

    float* rp = RESID ? (rout + (long long)b * NN) : nullptr;
    for (int idx = tid; idx < 32 * 32; idx += 256) {
        int oi = idx / 32, oj = idx - (idx / 32) * 32;
        int gi = Oi + oi, gj = Oj + oj;
        if (gi > 512 || gj > 512) continue;
        int li = HALO + oi, lj = HALO + oj;
        xo[(long long)gi * NG + gj] = xs[cur][li][lj];
        if (RESID) {
            float d = 0.f;
            if (gi >= 1 && gi <= 511 && gj >= 1 && gj <= 511) {
                float sum = 0.f;
#pragma unroll
                for (int u = 0; u < 2; u++) {
#pragma unroll
                    for (int v = 0; v < 2; v++) {
                        float av = as[li - 1 + u][lj - 1 + v];
                        float k0, k1, k2, k3;
                        if (u == 0 && v == 0) { k0 = c16; k1 = c23; k2 = c16; k3 = c13; }
                        else if (u == 0 && v == 1) { k0 = c23; k1 = c16; k2 = c13; k3 = c16; }
                        else if (u == 1 && v == 0) { k0 = c13; k1 = c16; k2 = c23; k3 = c16; }
                        else                        { k0 = c16; k1 = c13; k2 = c16; k3 = c23; }
                        sum += av * (k3 * xs[cur][li - 1 + u][lj - 1 + v]
                                   + k2 * xs[cur][li - 1 + u][lj + v]
                                   + k0 * xs[cur][li + u][lj - 1 + v]
                                   + k1 * xs[cur][li + u][lj + v]);
                    }
                }
                d = sum;
            }
            rp[(long long)gi * NG + gj] = fs[li][lj] - d;
        }
    }
}

__global__ __launch_bounds__(256)
void k_resid(const float* __restrict__ x, const float* __restrict__ f,
             const float* __restrict__ a, float* __restrict__ r)
{
    int b = blockIdx.z;
    int j = blockIdx.x * 16 + threadIdx.x;
    int i = blockIdx.y * 16 + threadIdx.y;
    if (i >= NG || j >= NG) return;
    long long o = (long long)b * NN + (long long)i * NG + j;
    float d = 0.f;
    if (i > 0 && j > 0 && i < NG - 1 && j < NG - 1)
        d = darcy_at(x + (long long)b * NN, a + (long long)b * NCC, i, j);
    r[o] = f[o] - d;
}

// ---------------------------------------------------------------------------
// Real SGEMM, double-buffered, 64x64/BK16, 256 threads, 4x4 microtile
// (proven R12 kernel), mirror epilogues.
// ---------------------------------------------------------------------------
template<int MIR>
__global__ __launch_bounds__(256)
void k_sgemm(const float* __restrict__ A, int lda, long long sA,
             const float* __restrict__ B, int ldb, long long sB,
             float* __restrict__ C, int ldc, long long sC,
             int M, int N, int K, float alpha)
{
    __shared__ float As[2][16][68];
    __shared__ float Bs[2][16][68];
    int b = blockIdx.z;
    A += (long long)b * sA;
    B += (long long)b * sB;
    C += (long long)b * sC;
    int tid = threadIdx.x;
    int m0 = blockIdx.y * 64, n0 = blockIdx.x * 64;
    int mt = (tid & 15) * 4;
    int nt = (tid >> 4) * 4;
    int ra_r[4], ra_c[4], rb_r[4], rb_c[4];
#pragma unroll
    for (int e = 0; e < 4; e++) {
        int idx = tid + e * 256;
        ra_r[e] = idx >> 4; ra_c[e] = idx & 15;
        rb_r[e] = idx >> 6; rb_c[e] = idx & 63;
    }
    float ra[4], rb[4];
    int ntiles = (K + 15) / 16;

#pragma unroll
    for (int e = 0; e < 4; e++) {
        int gm = m0 + ra_r[e], gk = ra_c[e];
        ra[e] = (gm < M && gk < K) ? A[(long long)gm * lda + gk] : 0.f;
        int gk2 = rb_r[e], gn = n0 + rb_c[e];
        rb[e] = (gk2 < K && gn < N) ? B[(long long)gk2 * ldb + gn] : 0.f;
    }
#pragma unroll
    for (int e = 0; e < 4; e++) {
        As[0][ra_c[e]][ra_r[e]] = ra[e];
        Bs[0][rb_r[e]][rb_c[e]] = rb[e];
    }
    __syncthreads();

    float acc[4][4] = {};
    for (int t = 0; t < ntiles; t++) {
        int kt = (t + 1) * 16;
        if (t + 1 < ntiles) {
#pragma unroll
            for (int e = 0; e < 4; e++) {
                int gm = m0 + ra_r[e], gk = kt + ra_c[e];
                ra[e] = (gm < M && gk < K) ? A[(long long)gm * lda + gk] : 0.f;
                int gk2 = kt + rb_r[e], gn = n0 + rb_c[e];
                rb[e] = (gk2 < K && gn < N) ? B[(long long)gk2 * ldb + gn] : 0.f;
            }
        }
        int cur = t & 1;
#pragma unroll
        for (int k = 0; k < 16; k++) {
            float av[4], bv[4];
#pragma unroll
            for (int i = 0; i < 4; i++) av[i] = As[cur][k][mt + i];
#pragma unroll
            for (int j = 0; j < 4; j++) bv[j] = Bs[cur][k][nt + j];
#pragma unroll
            for (int i = 0; i < 4; i++)
#pragma unroll
                for (int j = 0; j < 4; j++)
                    acc[i][j] = fmaf(av[i], bv[j], acc[i][j]);
        }
        if (t + 1 < ntiles) {
            int nxt = cur ^ 1;
#pragma unroll
            for (int e = 0; e < 4; e++) {
                As[nxt][ra_c[e]][ra_r[e]] = ra[e];
                Bs[nxt][rb_r[e]][rb_c[e]] = rb[e];
            }
        }
        __syncthreads();
    }

#pragma unroll
    for (int i = 0; i < 4; i++) {
        int gm = m0 + mt + i;
        if (gm >= M) continue;
#pragma unroll
        for (int j = 0; j < 4; j++) {
            int gn = n0 + nt + j;
            if (gn >= N) continue;
            float v = alpha * acc[i][j];
            if (MIR == 0) {
                C[(long long)gm * ldc + gn] = v;
            } else if (MIR == 1) {
                C[(long long)gm * ldc + 256 + gn] = v;
                if (gn > 0) C[(long long)gm * ldc + 256 - gn] = -v;
            } else {
                C[(long long)(256 + gm) * ldc + gn] = v;
                if (gm > 0) C[(long long)(256 - gm) * ldc + gn] = -v;
            }
        }
    }
}

// ---------------------------------------------------------------------------
// Combined corner fold: cD -> Af = [A1f ; A2f] (516 x 516).
// ---------------------------------------------------------------------------
__global__ void k_foldA(const float2* __restrict__ cD, float* __restrict__ Af)
{
    int b = blockIdx.z;
    int kc = blockIdx.x * 32 + threadIdx.x;
    int kr = blockIdx.y * 8 + threadIdx.y;
    if (kc >= NK || kr >= NK) return;
    const float2* D = cD + (long long)b * NN;
    bool pc = (kc >= 1 && kc <= 255);
    bool pr = (kr >= 1 && kr <= 255);
    float2 z = make_float2(0.f, 0.f);
    float2 pp = D[(long long)(255 + kr) * NG + 255 + kc];
    float2 pm = pc ? D[(long long)(255 + kr) * NG + 255 - kc] : z;
    float2 mp = pr ? D[(long long)(255 - kr) * NG + 255 + kc] : z;
    float2 mm = (pc && pr) ? D[(long long)(255 - kr) * NG + 255 - kc] : z;
    float* a1 = Af + (long long)b * NAF + (long long)kr * NK2;
    float* a2 = Af + (long long)b * NAF + (long long)(NK + kr) * NK2;
    a1[kc]      = (pp.x + pm.x) + (mp.x + mm.x);
    a1[NK + kc] = -((pp.y - pm.y) + (mp.y - mm.y));
    a2[kc]      = (pp.y + pm.y) - (mp.y + mm.y);
    a2[NK + kc] = (pp.x - pm.x) - (mp.x - mm.x);
}

// ---------------------------------------------------------------------------
// wt*ik2 helper
// ---------------------------------------------------------------------------
DINLINE float2 wtik_apply(float2 c, float wrv, float wiv, int p, int q)
{
    float dp = (float)(p - 256), dq = (float)(q - 256);
    float s = dp * dp + dq * dq;
    const float pi2 = 9.869604401089358f;
    float ik = (s == 0.f) ? 1.f : 1.f / (pi2 * s);
    float2 rr;
    rr.x = (c.x * wrv - c.y * wiv) * ik;
    rr.y = (c.x * wiv + c.y * wrv) * ik;
    return rr;
}

// ---------------------------------------------------------------------------
// Composed 7x7 forward conv (real input) + wt*ik2. 2 px/thread.
// ---------------------------------------------------------------------------
__global__ __launch_bounds__(256)
void k_conv7f(const float* __restrict__ X, float2* __restrict__ Y,
              const float2* __restrict__ wf,
              const float* __restrict__ wtr, const float* __restrict__ wti)
{
    int b = blockIdx.z;
    __shared__ float2 ws[49];
    int t = threadIdx.y * 16 + threadIdx.x;
    if (t < 49) ws[t] = wf[b * 49 + t];
    __syncthreads();
    int q = blockIdx.x * 16 + threadIdx.x;
    int p0 = blockIdx.y * 32 + 2 * threadIdx.y;
    if (q >= NG || p0 >= NG) return;
    bool hasP1 = (p0 + 1 < NG);
    const float* Xb = X + (long long)b * NN;
    float2 a0 = make_float2(0.f, 0.f), a1 = make_float2(0.f, 0.f);
    int pB = blockIdx.y * 32, qB = blockIdx.x * 16;
    bool interior = (pB >= 3) && (pB + 34 <= NG - 1) && (qB >= 3) && (qB + 18 <= NG - 1);
    if (interior) {
#pragma unroll
        for (int r = 0; r < 8; r++) {
            int row = p0 - 3 + r;
            float xr[7];
#pragma unroll
            for (int c = 0; c < 7; c++) xr[c] = Xb[(long long)row * NG + q - 3 + c];
#pragma unroll
            for (int dx = 0; dx < 7; dx++) {
                if (r < 7) {
                    float2 w = ws[r * 7 + dx];
                    a0.x = fmaf(xr[dx], w.x, a0.x);
                    a0.y = fmaf(xr[dx], w.y, a0.y);
                }
                if (r >= 1) {
                    float2 w = ws[(r - 1) * 7 + dx];
                    a1.x = fmaf(xr[dx], w.x, a1.x);
                    a1.y = fmaf(xr[dx], w.y, a1.y);
                }
            }
        }
    } else {
#pragma unroll
        for (int r = 0; r < 8; r++) {
            int row = p0 - 3 + r;
            bool vr = (row >= 0 && row < NG);
            float xr[7];
#pragma unroll
            for (int c = 0; c < 7; c++) {
                int col = q - 3 + c;
                xr[c] = (vr && col >= 0 && col < NG) ? Xb[(long long)row * NG + col] : 0.f;
            }
#pragma unroll
            for (int dx = 0; dx < 7; dx++) {
                if (r < 7) {
                    float2 w = ws[r * 7 + dx];
                    a0.x = fmaf(xr[dx], w.x, a0.x);
                    a0.y = fmaf(xr[dx], w.y, a0.y);
                }
                if (r >= 1) {
                    float2 w = ws[(r - 1) * 7 + dx];
                    a1.x = fmaf(xr[dx], w.x, a1.x);
                    a1.y = fmaf(xr[dx], w.y, a1.y);
                }
            }
        }
    }
    float2* Yb = Y + (long long)b * NN;
    {
        long long o = (long long)b * NN + (long long)p0 * NG + q;
        Yb[(long long)p0 * NG + q] = wtik_apply(a0, wtr[o], wti[o], p0, q);
    }
    if (hasP1) {
        long long o = (long long)b * NN + (long long)(p0 + 1) * NG + q;
        Yb[(long long)(p0 + 1) * NG + q] = wtik_apply(a1, wtr[o], wti[o], p0 + 1, q);
    }
}

// ---------------------------------------------------------------------------
// Composed 7x7 backward conv (complex input), taps = conj(wf^T). 2 px/thread.
// ---------------------------------------------------------------------------
__global__ __launch_bounds__(256)
void k_conv7b(const float2* __restrict__ X, float2* __restrict__ Y,
              const float2* __restrict__ wf)
{
    int b = blockIdx.z;
    __shared__ float2 ws[49];
    int t = threadIdx.y * 16 + threadIdx.x;
    if (t < 49) {
        int dy = t / 7, dx = t % 7;
        float2 v = wf[b * 49 + dx * 7 + dy];
        ws[t] = make_float2(v.x, -v.y);
    }
    __syncthreads();
    int q = blockIdx.x * 16 + threadIdx.x;
    int p0 = blockIdx.y * 32 + 2 * threadIdx.y;
    if (q >= NG || p0 >= NG) return;
    bool hasP1 = (p0 + 1 < NG);
    const float2* Xb = X + (long long)b * NN;
    float2 a0 = make_float2(0.f, 0.f), a1 = make_float2(0.f, 0.f);
    int pB = blockIdx.y * 32, qB = blockIdx.x * 16;
    bool interior = (pB >= 3) && (pB + 34 <= NG - 1) && (qB >= 3) && (qB + 18 <= NG - 1);
    if (interior) {
#pragma unroll
        for (int r = 0; r < 8; r++) {
            int row = p0 - 3 + r;
            float2 xr[7];
#pragma unroll
            for (int c = 0; c < 7; c++) xr[c] = Xb[(long long)row * NG + q - 3 + c];
#pragma unroll
            for (int dx = 0; dx < 7; dx++) {
                if (r < 7) a0 = cmad(a0, xr[dx], ws[r * 7 + dx]);
                if (r >= 1) a1 = cmad(a1, xr[dx], ws[(r - 1) * 7 + dx]);
            }
        }
    } else {
#pragma unroll
        for (int r = 0; r < 8; r++) {
            int row = p0 - 3 + r;
            bool vr = (row >= 0 && row < NG);
            float2 xr[7];
#pragma unroll
            for (int c = 0; c < 7; c++) {
                int col = q - 3 + c;
                xr[c] = (vr && col >= 0 && col < NG)
                      ? Xb[(long long)row * NG + col] : make_float2(0.f, 0.f);
            }
#pragma unroll
            for (int dx = 0; dx < 7; dx++) {
                if (r < 7) a0 = cmad(a0, xr[dx], ws[r * 7 + dx]);
                if (r >= 1) a1 = cmad(a1, xr[dx], ws[(r - 1) * 7 + dx]);
            }
        }
    }
    float2* Yb = Y + (long long)b * NN;
    Yb[(long long)p0 * NG + q] = a0;
    if (hasP1) Yb[(long long)(p0 + 1) * NG + q] = a1;
}

// ---------------------------------------------------------------------------
// Strip conv: exact sequential 3x3 conv on a boundary frame of width FW.
// ---------------------------------------------------------------------------
template<int CO, int CI, int FW, bool REAL_IN, bool WTIK>
__global__ __launch_bounds__(256)
void k_conv_strip(const void* __restrict__ Xv, float2* __restrict__ Y,
                  const float* __restrict__ wr, const float* __restrict__ wi,
                  int conjt, const float* __restrict__ wtr,
                  const float* __restrict__ wti)
{
    int b = blockIdx.y;
    __shared__ float2 ws[CO * CI * 9];
    int t = threadIdx.x;
    if (t < CO * CI * 9) {
        int o = t / (CI * 9), rem = t % (CI * 9), i = rem / 9, tap = rem % 9;
        int dy = tap / 3, dx = tap % 3;
        long long widx;
        float sgn;
        if (conjt) { widx = ((long long)(b * CI + i) * CO + o) * 9 + dx * 3 + dy; sgn = -1.f; }
        else       { widx = ((long long)(b * CO + o) * CI + i) * 9 + dy * 3 + dx; sgn =  1.f; }
        ws[t] = make_float2(wr[widx], sgn * wi[widx]);
    }
    __syncthreads();

    const int nTop = FW * NG;
    const int nSide = (NG - 2 * FW) * FW;
    const int total = 2 * nTop + 2 * nSide;
    int idx = blockIdx.x * 256 + t;
    if (idx >= total) return;
    int p, q;
    if (idx < nTop)            { p = idx / NG; q = idx - p * NG; }
    else if (idx < 2 * nTop)   { int k2 = idx - nTop; p = NG - FW + k2 / NG; q = k2 % NG; }
    else if (idx < 2 * nTop + nSide) { int k2 = idx - 2 * nTop; p = FW + k2 / FW; q = k2 % FW; }
    else                       { int k2 = idx - 2 * nTop - nSide; p = FW + k2 / FW; q = NG - FW + k2 % FW; }

    float2 acc[CO];
#pragma unroll
    for (int o = 0; o < CO; o++) acc[o] = make_float2(0.f, 0.f);
#pragma unroll
    for (int i = 0; i < CI; i++) {
#pragma unroll
        for (int dy = 0; dy < 3; dy++) {
            int ii = p + dy - 1;
#pragma unroll
            for (int dx = 0; dx < 3; dx++) {
                int jj = q + dx - 1;
                float2 xv = make_float2(0.f, 0.f);
                if (ii >= 0 && ii < NG && jj >= 0 && jj < NG) {
                    if (REAL_IN) {
                        const float* Xb = (const float*)Xv + (long long)b * NN;
                        xv.x = Xb[(long long)ii * NG + jj];
                    } else {
                        const float2* Xb = (const float2*)Xv + (long long)b * CI * NN;
                        xv = Xb[(long long)i * NN + (long long)ii * NG + jj];
                    }
                }
                int tap = dy * 3 + dx;
#pragma unroll
                for (int o = 0; o < CO; o++)
                    acc[o] = cmad(acc[o], xv, ws[(o * CI + i) * 9 + tap]);
            }
        }
    }
    float2* Yb = Y + (long long)b * CO * NN;
    long long po = (long long)p * NG + q;
    if (WTIK) {
        long long o = (long long)b * NN + po;
        Yb[po] = wtik_apply(acc[0], wtr[o], wti[o], p, q);
    } else {
#pragma unroll
        for (int o = 0; o < CO; o++) Yb[(long long)o * NN + po] = acc[o];
    }
}

// ---------------------------------------------------------------------------
// Reductions (deterministic, double accumulation)
// ---------------------------------------------------------------------------
__global__ __launch_bounds__(256)
void k_alpha_part(const float* __restrict__ r, const float* __restrict__ e,
                  const float* __restrict__ a, double* __restrict__ p1,
                  double* __restrict__ p2)
{
    int b = blockIdx.y;
    const float* rb = r + (long long)b * NN;
    const float* eb = e + (long long)b * NN;
    const float* ab = a + (long long)b * NCC;
    double num = 0.0, den = 0.0;
    for (long long idx = (long long)blockIdx.x * 256 + threadIdx.x; idx < NN;
         idx += (long long)gridDim.x * 256) {
        int i = (int)(idx / NG), j = (int)(idx - (long long)i * NG);
        float ev = eb[idx];
        num += (double)(rb[idx] * ev);
        if (i > 0 && j > 0 && i < NG - 1 && j < NG - 1) {
            float d = darcy_at(eb, ab, i, j);
            den += (double)(d * ev);
        }
    }
    __shared__ double s1[256], s2[256];
    int t = threadIdx.x;
    s1[t] = num; s2[t] = den;
    __syncthreads();
    for (int s = 128; s > 0; s >>= 1) {
        if (t < s) { s1[t] += s1[t + s]; s2[t] += s2[t + s]; }
        __syncthreads();
    }
    if (t == 0) { p1[b * NBLK_A + blockIdx.x] = s1[0]; p2[b * NBLK_A + blockIdx.x] = s2[0]; }
}

__global__ void k_alpha_fin(const double* __restrict__ p1,
                            const double* __restrict__ p2,
                            float* __restrict__ alpha)
{
    int b = blockIdx.x;
    __shared__ double s1[256], s2[256];
    double n = 0.0, d = 0.0;
    for (int i = threadIdx.x; i < NBLK_A; i += 256) {
        n += p1[b * NBLK_A + i]; d += p2[b * NBLK_A + i];
    }
    int t = threadIdx.x;
    s1[t] = n; s2[t] = d;
    __syncthreads();
    for (int s = 128; s > 0; s >>= 1) {
        if (t < s) { s1[t] += s1[t + s]; s2[t] += s2[t + s]; }
        __syncthreads();
    }
    if (t == 0) alpha[b] = (float)(s1[0] / s2[0]);
}

__global__ void k_update(float* __restrict__ x, const float* __restrict__ e,
                         const float* __restrict__ alpha)
{
    int b = blockIdx.z;
    int j = blockIdx.x * 16 + threadIdx.x + 1;
    int i = blockIdx.y * 16 + threadIdx.y + 1;
    if (i > NI || j > NI) return;
    long long o = (long long)b * NN + (long long)i * NG + j;
    x[o] = fmaf(alpha[b], e[o], x[o]);
}

__global__ __launch_bounds__(256)
void k_norm_part(const float* __restrict__ r, const float* __restrict__ f,
                 double* __restrict__ p1, double* __restrict__ p2)
{
    double sr = 0.0, sf = 0.0;
    long long tot = (long long)NB * NN;
    for (long long idx = (long long)blockIdx.x * 256 + threadIdx.x; idx < tot;
         idx += (long long)gridDim.x * 256) {
        float rv = r[idx], fv = f[idx];
        sr += (double)rv * rv;
        sf += (double)fv * fv;
    }
    __shared__ double s1[256], s2[256];
    int t = threadIdx.x;
    s1[t] = sr; s2[t] = sf;
    __syncthreads();
    for (int s = 128; s > 0; s >>= 1) {
        if (t < s) { s1[t] += s1[t + s]; s2[t] += s2[t + s]; }
        __syncthreads();
    }
    if (t == 0) { p1[blockIdx.x] = s1[0]; p2[blockIdx.x] = s2[0]; }
}

__global__ void k_norm_fin(const double* __restrict__ p1,
                           const double* __restrict__ p2,
                           float* __restrict__ out)
{
    __shared__ double s1[256], s2[256];
    double a = 0.0, b = 0.0;
    for (int i = threadIdx.x; i < NBLK_N; i += 256) { a += p1[i]; b += p2[i]; }
    int t = threadIdx.x;
    s1[t] = a; s2[t] = b;
    __syncthreads();
    for (int s = 128; s > 0; s >>= 1) {
        if (t < s) { s1[t] += s1[t + s]; s2[t] += s2[t + s]; }
        __syncthreads();
    }
    if (t == 0) out[0] = (float)sqrt(s1[0] / s2[0]);
}

// ---------------------------------------------------------------------------
// Host orchestration
// ---------------------------------------------------------------------------
template<typename T>
static T* sym_addr(const void* sym)
{
    void* p = nullptr;
    cudaGetSymbolAddress(&p, sym);
    return (T*)p;
}

static inline int strip_blocks(int FW)
{
    int nTop = FW * NG, nSide = (NG - 2 * FW) * FW;
    int total = 2 * nTop + 2 * nSide;
    return (total + 255) / 256;
}

extern "C" void kernel_launch(void* const* d_in, const int* in_sizes, int n_in,
                              void* d_out, int out_size)
{
    const float* f    = (const float*)d_in[0];
    const float* coef = (const float*)d_in[1];
    const float* w1r = (const float*)d_in[3];
    const float* w1i = (const float*)d_in[4];
    const float* w2r = (const float*)d_in[5];
    const float* w2i = (const float*)d_in[6];
    const float* w3r = (const float*)d_in[7];
    const float* w3i = (const float*)d_in[8];
    const float* wtr = (const float*)d_in[9];
    const float* wti = (const float*)d_in[10];

    float*  x    = sym_addr<float>(g_x);
    float*  x2   = sym_addr<float>(g_x2);
    float*  r    = sym_addr<float>(g_r);
    float*  e    = sym_addr<float>(g_e);
    float*  rh   = sym_addr<float>(g_rh);
    float*  dinv = sym_addr<float>(g_dinv);
    float*  S    = sym_addr<float>(g_S);
    float*  St   = sym_addr<float>(g_St);
    float*  U    = sym_addr<float>(g_U);
    float2* cA   = sym_addr<float2>(g_cA);
    float2* cB   = sym_addr<float2>(g_cB);
    float2* cC   = sym_addr<float2>(g_cC);
    float2* cD   = sym_addr<float2>(g_cD);
    float2* wf   = sym_addr<float2>(g_wf);
    float*  Af   = sym_addr<float>(g_Af);
    float*  F    = sym_addr<float>(g_F);
    float*  Bm   = sym_addr<float>(g_Bm);
    float*  Em   = sym_addr<float>(g_Em);
    double* pd1  = sym_addr<double>(g_pd1);
    double* pd2  = sym_addr<double>(g_pd2);
    float*  alph = sym_addr<float>(g_alpha);

    dim3 blk2(16, 16);
    dim3 gInt((NI + 15) / 16, (NI + 15) / 16, NB);
    dim3 gFull((NG + 15) / 16, (NG + 15) / 16, NB);
    dim3 gConv((NG + 15) / 16, (NG + 31) / 32, NB);
    dim3 gJac((NG + 31) / 32, (NG + 31) / 32, NB);

    dim3 gS5(strip_blocks(5), NB);
    dim3 gS4(strip_blocks(4), NB);
    dim3 gS3(strip_blocks(3), NB);

    dim3 blkF(32, 8);
    dim3 gFo((NK + 31) / 32, (NK + 7) / 8, NB);

    // ---- setup (1 segmented kernel + conv composition) ----
    {
        long long total = (long long)NB * NN + (long long)NG * NI
                        + (long long)NK2 * NI + (long long)NI * NK2
                        + (long long)NB * NII;
        k_setup<<<(int)((total + 255) / 256), 256>>>(x, x2, e, S, St, Bm, Em,
                                                     coef, dinv);
        k_compose<<<NB, 64>>>(w1r, w1i, w2r, w2i, w3r, w3i, wf);
    }

    for (int step = 0; step < KSTEPS; step++) {
        // ---- 10 Jacobi sweeps (2 fused kernels) + residual ----
        k_jacobi5<false><<<gJac, 256>>>(x, x2, f, coef, dinv, nullptr);
        k_jacobi5<true ><<<gJac, 256>>>(x2, x, f, coef, dinv, r);

        // ---- forward sine transform (odd symmetry fused in epilogue) ----
        {
            dim3 g((257 + 63) / 64, (NI + 63) / 64, NB);
            k_sgemm<1><<<g, 256>>>(r + NG + 1, NG, NN,
                                   St + 256, NG, 0,
                                   U, NG, NIG,
                                   NI, 257, NI, 1.f);
        }
        {
            dim3 g((NG + 63) / 64, (257 + 63) / 64, NB);
            k_sgemm<2><<<g, 256>>>(S + 256 * NI, NI, 0,
                                   U, NG, NIG,
                                   rh, NG, NN,
                                   257, NG, NI, -1.f / (512.f * 512.f));
        }

        // ---- forward conv chain: composed 7x7 + exact ring correction ----
        k_conv7f<<<gConv, blk2>>>(rh, cC, wf, wtr, wti);
        k_conv_strip<4, 1, 5, true,  false><<<gS5, 256>>>(rh, cA, w1r, w1i, 0, nullptr, nullptr);
        k_conv_strip<4, 4, 4, false, false><<<gS4, 256>>>(cA, cB, w2r, w2i, 0, nullptr, nullptr);
        k_conv_strip<1, 4, 3, false, true ><<<gS3, 256>>>(cB, cC, w3r, w3i, 0, wtr, wti);

        // ---- backward conv chain: composed conj(wf^T) + ring correction ----
        k_conv7b<<<gConv, blk2>>>(cC, cD, wf);
        k_conv_strip<4, 1, 5, false, false><<<gS5, 256>>>(cC, cA, w3r, w3i, 1, nullptr, nullptr);
        k_conv_strip<4, 4, 4, false, false><<<gS4, 256>>>(cA, cB, w2r, w2i, 1, nullptr, nullptr);
        k_conv_strip<1, 4, 3, false, false><<<gS3, 256>>>(cB, cD, w1r, w1i, 1, nullptr, nullptr);

        // ---- inverse transform: corner-fold then 2 real GEMMs ----
        k_foldA<<<gFo, blkF>>>(cD, Af);
        {
            dim3 g((NI + 63) / 64, (NK2 + 63) / 64, NB);
            k_sgemm<0><<<g, 256>>>(Af, NK2, NAF, Bm, NI, 0, F, NI, NF,
                                   NK2, NI, NK2, 1.f);
        }
        {
            dim3 g((NI + 63) / 64, (NI + 63) / 64, NB);
            k_sgemm<0><<<g, 256>>>(Em, NK2, 0, F, NI, NF, e + NG + 1, NG, NN,
                                   NI, NI, NK2, 1.f);
        }

        // ---- alpha and update ----
        {
            dim3 g(NBLK_A, NB);
            k_alpha_part<<<g, 256>>>(r, e, coef, pd1, pd2);
            k_alpha_fin<<<NB, 256>>>(pd1, pd2, alph);
            k_update<<<gInt, blk2>>>(x, e, alph);
        }
    }

    // ---- final relative residual norm ----
    k_resid<<<gFull, blk2>>>(x, f, coef, r);
    k_norm_part<<<NBLK_N, 256>>>(r, f, pd1, pd2);
    k_norm_fin<<<1, 256>>>(pd1, pd2, (float*)d_out);
}

// round 16
// speedup vs baseline: 1.1225x; 1.0078x over previous
#include <cuda_runtime.h>
#include <math.h>

#define DINLINE __device__ __forceinline__

// ---------------------------------------------------------------------------
// Fixed problem dimensions (B=4, grid 513, coef 512, epoch=101 -> K=2)
// ---------------------------------------------------------------------------
namespace fns {
constexpr int NB = 4;
constexpr int NG = 513;
constexpr int NI = 511;
constexpr int NC = 512;
constexpr int NK = 258;
constexpr int NK2 = 516;
constexpr long long NN  = (long long)NG * NG;
constexpr long long NCC = (long long)NC * NC;
constexpr long long NII = (long long)NI * NI;
constexpr long long NIG = (long long)NI * NG;
constexpr long long NAF = (long long)NK2 * NK2;  // folded A: 516 x 516
constexpr long long NF  = (long long)NK2 * NI;   // 516 x 511
constexpr int NBLK_A = 128;
constexpr int NBLK_N = 256;
constexpr int KSTEPS = 2;
}
using namespace fns;

// ---------------------------------------------------------------------------
// Static device scratch
// ---------------------------------------------------------------------------
__device__ float  g_x   [NB * NN];
__device__ float  g_x2  [NB * NN];
__device__ float  g_r   [NB * NN];
__device__ float  g_e   [NB * NN];
__device__ float  g_rh  [NB * NN];
__device__ float  g_dinv[NB * NII];
__device__ float  g_S   [NG * (long long)NI];  // S[p][j], ld=NI
__device__ float  g_St  [NIG];                 // St[j][p], ld=NG
__device__ float  g_U   [NB * NIG];            // 511 x 513, ld=NG
__device__ float2 g_cA  [NB * 4 * NN];         // strip scratch stage-1
__device__ float2 g_cB  [NB * 4 * NN];         // strip scratch stage-2
__device__ float2 g_cC  [NB * NN];             // spectral signal
__device__ float2 g_cD  [NB * NN];             // backward-conv output
__device__ float2 g_wf  [NB * 49];             // composed 7x7 forward taps
__device__ float  g_Af  [NB * NAF];            // folded [A1f ; A2f], 516 x 516
__device__ float  g_F   [NB * NF];             // [A ; B], 516 x 511
__device__ float  g_Bm  [NF];                  // [C ; S], 516 x 511 (const)
__device__ float  g_Em  [(long long)NI * NK2]; // [Cos | Sin], 511 x 516 (const)
__device__ double g_pd1 [2048];
__device__ double g_pd2 [2048];
__device__ float  g_alpha[NB];

// ---------------------------------------------------------------------------
// Darcy FEM 9-point stencil (global-memory form, for alpha / resnorm)
// ---------------------------------------------------------------------------
DINLINE float darcy_at(const float* __restrict__ x,
                       const float* __restrict__ a, int i, int j)
{
    const float c23 = 2.f / 3.f, c16 = -1.f / 6.f, c13 = -1.f / 3.f;
    float s = 0.f;
#pragma unroll
    for (int u = 0; u < 2; u++) {
#pragma unroll
        for (int v = 0; v < 2; v++) {
            int I = i - 1 + u, J = j - 1 + v;
            float av = a[(long long)I * NC + J];
            float k0, k1, k2, k3;
            if (u == 0 && v == 0) { k0 = c16; k1 = c23; k2 = c16; k3 = c13; }
            else if (u == 0 && v == 1) { k0 = c23; k1 = c16; k2 = c13; k3 = c16; }
            else if (u == 1 && v == 0) { k0 = c13; k1 = c16; k2 = c23; k3 = c16; }
            else                        { k0 = c16; k1 = c13; k2 = c16; k3 = c23; }
            s += av * (k3 * x[(long long)I * NG + J]
                     + k2 * x[(long long)I * NG + J + 1]
                     + k0 * x[(long long)(I + 1) * NG + J]
                     + k1 * x[(long long)(I + 1) * NG + J + 1]);
        }
    }
    return s;
}

DINLINE float2 cmad(float2 acc, float2 a, float2 b)
{
    acc.x = fmaf(a.x, b.x, fmaf(-a.y, b.y, acc.x));
    acc.y = fmaf(a.x, b.y, fmaf(a.y, b.x, acc.y));
    return acc;
}

// ---------------------------------------------------------------------------
// One segmented setup kernel: zero x/x2/e, S/St, Bm, Em, dinv
// ---------------------------------------------------------------------------
__global__ void k_setup(float* __restrict__ x, float* __restrict__ x2,
                        float* __restrict__ e,
                        float* __restrict__ S, float* __restrict__ St,
                        float* __restrict__ Bm, float* __restrict__ Em,
                        const float* __restrict__ a, float* __restrict__ dinv)
{
    long long idx = (long long)blockIdx.x * blockDim.x + threadIdx.x;
    const long long T0 = (long long)NB * NN;
    const long long T1 = T0 + (long long)NG * NI;
    const long long T2 = T1 + (long long)NK2 * NI;
    const long long T3 = T2 + (long long)NI * NK2;
    const long long T4 = T3 + (long long)NB * NII;
    if (idx < T0) {
        x[idx] = 0.f; x2[idx] = 0.f; e[idx] = 0.f;
    } else if (idx < T1) {
        long long t = idx - T0;
        int p = (int)(t / NI), j = (int)(t - (long long)p * NI);
        int m = (j + 1) * (p - 256);
        int mm = ((m % 1024) + 1024) % 1024;
        float v = sinpif((float)mm / 512.f);
        S[t] = v;
        St[(long long)j * NG + p] = v;
    } else if (idx < T2) {
        long long t = idx - T1;
        int k2 = (int)(t / NI), s = (int)(t - (long long)k2 * NI);
        int k = (k2 < NK) ? k2 : k2 - NK;
        int tm = (2 * k * s) % 2050;
        float xr = (float)tm / 1025.f;
        Bm[t] = (k2 < NK) ? cospif(xr) : -sinpif(xr);
    } else if (idx < T3) {
        long long t = idx - T2;
        int s = (int)(t / NK2), k2 = (int)(t - (long long)s * NK2);
        int k = (k2 < NK) ? k2 : k2 - NK;
        int tm = (2 * s * k) % 2050;
        float xr = (float)tm / 1025.f;
        Em[t] = (k2 < NK) ? cospif(xr) : sinpif(xr);
    } else if (idx < T4) {
        long long t = idx - T3;
        int b = (int)(t / NII);
        long long rem = t - (long long)b * NII;
        int p = (int)(rem / NI), q = (int)(rem - (long long)p * NI);
        const float* ap = a + (long long)b * NCC;
        float s = ap[(long long)p * NC + q] + ap[(long long)p * NC + q + 1]
                + ap[(long long)(p + 1) * NC + q] + ap[(long long)(p + 1) * NC + q + 1];
        dinv[t] = 1.f / ((2.f / 3.f) * s);
    }
}

// ---------------------------------------------------------------------------
// Compose the 3-stage complex conv chain into one 7x7 tap set.
// ---------------------------------------------------------------------------
__global__ void k_compose(const float* __restrict__ w1r, const float* __restrict__ w1i,
                          const float* __restrict__ w2r, const float* __restrict__ w2i,
                          const float* __restrict__ w3r, const float* __restrict__ w3i,
                          float2* __restrict__ wf)
{
    int b = blockIdx.x;
    int t = threadIdx.x;
    if (t >= 49) return;
    int dy = t / 7, dx = t % 7;
    float accr = 0.f, acci = 0.f;
    for (int c = 0; c < 4; c++) {
        for (int o = 0; o < 4; o++) {
            for (int a = 0; a < 9; a++) {
                int ay = a / 3, ax = a % 3;
                float r1 = w1r[(b * 4 + c) * 9 + a];
                float i1 = w1i[(b * 4 + c) * 9 + a];
                for (int bt = 0; bt < 9; bt++) {
                    int by = bt / 3, bx = bt % 3;
                    int cy = dy - ay - by, cx = dx - ax - bx;
                    if (cy < 0 || cy > 2 || cx < 0 || cx > 2) continue;
                    float r2 = w2r[((b * 4 + o) * 4 + c) * 9 + bt];
                    float i2 = w2i[((b * 4 + o) * 4 + c) * 9 + bt];
                    float r3 = w3r[(b * 4 + o) * 9 + cy * 3 + cx];
                    float i3 = w3i[(b * 4 + o) * 9 + cy * 3 + cx];
                    float tr = r1 * r2 - i1 * i2;
                    float ti = r1 * i2 + i1 * r2;
                    accr += tr * r3 - ti * i3;
                    acci += tr * i3 + ti * r3;
                }
            }
        }
    }
    wf[b * 49 + t] = make_float2(accr, acci);
}

// ---------------------------------------------------------------------------
// Fused Jacobi: 5 sweeps in one kernel via smem (44x44 tile, halo 6).
// Boundary encoded in ds (0.75*dinv, 0 on boundary). UPD fuses the pending
// x += alpha*e update into the smem load (bit-identical: e=0 on boundary).
// RESID variant also writes r = f - A(x_final) for its 32x32 output tile.
// ---------------------------------------------------------------------------
template<bool RESID, bool UPD>
__global__ __launch_bounds__(256)
void k_jacobi5(const float* __restrict__ xin, float* __restrict__ xout,
               const float* __restrict__ f, const float* __restrict__ a,
               const float* __restrict__ dinv, float* __restrict__ rout,
               const float* __restrict__ eupd, const float* __restrict__ alpha)
{
    constexpr int W = 44, HALO = 6, SW = 5;
    __shared__ float xs[2][W][W];
    __shared__ float as[W][W], fs[W][W], ds[W][W];
    int b = blockIdx.z;
    int Oi = blockIdx.y * 32, Oj = blockIdx.x * 32;
    const float* xp = xin + (long long)b * NN;
    const float* fp = f + (long long)b * NN;
    const float* ap = a + (long long)b * NCC;
    const float* dp = dinv + (long long)b * NII;
    float* xo = xout + (long long)b * NN;
    int tid = threadIdx.x;
    float al = 0.f;
    const float* ep = nullptr;
    if (UPD) { al = alpha[b]; ep = eupd + (long long)b * NN; }

    for (int idx = tid; idx < W * W; idx += 256) {
        int li = idx / W, lj = idx - (idx / W) * W;
        int gi = Oi - HALO + li, gj = Oj - HALO + lj;
        bool inx = (gi >= 0 && gi <= 512 && gj >= 0 && gj <= 512);
        float xv = inx ? xp[(long long)gi * NG + gj] : 0.f;
        if (UPD && inx) xv = fmaf(al, ep[(long long)gi * NG + gj], xv);
        xs[0][li][lj] = xv;
        fs[li][lj]    = inx ? fp[(long long)gi * NG + gj] : 0.f;
        bool ina = (gi >= 0 && gi <= 511 && gj >= 0 && gj <= 511);
        as[li][lj] = ina ? ap[(long long)gi * NC + gj] : 0.f;
        bool ind = (gi >= 1 && gi <= 511 && gj >= 1 && gj <= 511);
        ds[li][lj] = ind ? 0.75f * dp[(long long)(gi - 1) * NI + (gj - 1)] : 0.f;
    }
    __syncthreads();

    const float c23 = 2.f / 3.f, c16 = -1.f / 6.f, c13 = -1.f / 3.f;
    int cur = 0;
    for (int s = 1; s <= SW; s++) {
        for (int idx = tid; idx < W * W; idx += 256) {
            int li = idx / W, lj = idx - (idx / W) * W;
            if (li < s || li >= W - s || lj < s || lj >= W - s) continue;
            float old = xs[cur][li][lj];
            float sum = 0.f;
#pragma unroll
            for (int u = 0; u < 2; u++) {
#pragma unroll
                for (int v = 0; v < 2; v++) {
                    float av = as[li - 1 + u][lj - 1 + v];
                    float k0, k1, k2, k3;
                    if (u == 0 && v == 0) { k0 = c16; k1 = c23; k2 = c16; k3 = c13; }
                    else if (u == 0 && v == 1) { k0 = c23; k1 = c16; k2 = c13; k3 = c16; }
                    else if (u == 1 && v == 0) { k0 = c13; k1 = c16; k2 = c23; k3 = c16; }
                    else                        { k0 = c16; k1 = c13; k2 = c16; k3 = c23; }
                    sum += av * (k3 * xs[cur][li - 1 + u][lj - 1 + v]
                               + k2 * xs[cur][li - 1 + u][lj + v]
                               + k0 * xs[cur][li + u][lj - 1 + v]
                               + k1 * xs[cur][li + u][lj + v]);
                }
            }
            xs[cur ^ 1][li][lj] = fmaf(ds[li][lj], fs[li][lj] - sum, old);
        }
        __syncthreads();
        cur ^= 1;
    }

    float* rp = RESID ? (rout + (long long)b * NN) : nullptr;
    for (int idx = tid; idx < 32 * 32; idx += 256) {
        int oi = idx / 32, oj = idx - (idx / 32) * 32;
        int gi = Oi + oi, gj = Oj + oj;
        if (gi > 512 || gj > 512) continue;
        int li = HALO + oi, lj = HALO + oj;
        xo[(long long)gi * NG + gj] = xs[cur][li][lj];
        if (RESID) {
            float d = 0.f;
            if (gi >= 1 && gi <= 511 && gj >= 1 && gj <= 511) {
                float sum = 0.f;
#pragma unroll
                for (int u = 0; u < 2; u++) {
#pragma unroll
                    for (int v = 0; v < 2; v++) {
                        float av = as[li - 1 + u][lj - 1 + v];
                        float k0, k1, k2, k3;
                        if (u == 0 && v == 0) { k0 = c16; k1 = c23; k2 = c16; k3 = c13; }
                        else if (u == 0 && v == 1) { k0 = c23; k1 = c16; k2 = c13; k3 = c16; }
                        else if (u == 1 && v == 0) { k0 = c13; k1 = c16; k2 = c23; k3 = c16; }
                        else                        { k0 = c16; k1 = c13; k2 = c16; k3 = c23; }
                        sum += av * (k3 * xs[cur][li - 1 + u][lj - 1 + v]
                                   + k2 * xs[cur][li - 1 + u][lj + v]
                                   + k0 * xs[cur][li + u][lj - 1 + v]
                                   + k1 * xs[cur][li + u][lj + v]);
                    }
                }
                d = sum;
            }
            rp[(long long)gi * NG + gj] = fs[li][lj] - d;
        }
    }
}

// ---------------------------------------------------------------------------
// Real SGEMM, double-buffered, 64x64/BK16, 256 threads, 4x4 microtile
// (proven R12 kernel), mirror epilogues.
// ---------------------------------------------------------------------------
template<int MIR>
__global__ __launch_bounds__(256)
void k_sgemm(const float* __restrict__ A, int lda, long long sA,
             const float* __restrict__ B, int ldb, long long sB,
             float* __restrict__ C, int ldc, long long sC,
             int M, int N, int K, float alpha)
{
    __shared__ float As[2][16][68];
    __shared__ float Bs[2][16][68];
    int b = blockIdx.z;
    A += (long long)b * sA;
    B += (long long)b * sB;
    C += (long long)b * sC;
    int tid = threadIdx.x;
    int m0 = blockIdx.y * 64, n0 = blockIdx.x * 64;
    int mt = (tid & 15) * 4;
    int nt = (tid >> 4) * 4;
    int ra_r[4], ra_c[4], rb_r[4], rb_c[4];
#pragma unroll
    for (int e = 0; e < 4; e++) {
        int idx = tid + e * 256;
        ra_r[e] = idx >> 4; ra_c[e] = idx & 15;
        rb_r[e] = idx >> 6; rb_c[e] = idx & 63;
    }
    float ra[4], rb[4];
    int ntiles = (K + 15) / 16;

#pragma unroll
    for (int e = 0; e < 4; e++) {
        int gm = m0 + ra_r[e], gk = ra_c[e];
        ra[e] = (gm < M && gk < K) ? A[(long long)gm * lda + gk] : 0.f;
        int gk2 = rb_r[e], gn = n0 + rb_c[e];
        rb[e] = (gk2 < K && gn < N) ? B[(long long)gk2 * ldb + gn] : 0.f;
    }
#pragma unroll
    for (int e = 0; e < 4; e++) {
        As[0][ra_c[e]][ra_r[e]] = ra[e];
        Bs[0][rb_r[e]][rb_c[e]] = rb[e];
    }
    __syncthreads();

    float acc[4][4] = {};
    for (int t = 0; t < ntiles; t++) {
        int kt = (t + 1) * 16;
        if (t + 1 < ntiles) {
#pragma unroll
            for (int e = 0; e < 4; e++) {
                int gm = m0 + ra_r[e], gk = kt + ra_c[e];
                ra[e] = (gm < M && gk < K) ? A[(long long)gm * lda + gk] : 0.f;
                int gk2 = kt + rb_r[e], gn = n0 + rb_c[e];
                rb[e] = (gk2 < K && gn < N) ? B[(long long)gk2 * ldb + gn] : 0.f;
            }
        }
        int cur = t & 1;
#pragma unroll
        for (int k = 0; k < 16; k++) {
            float av[4], bv[4];
#pragma unroll
            for (int i = 0; i < 4; i++) av[i] = As[cur][k][mt + i];
#pragma unroll
            for (int j = 0; j < 4; j++) bv[j] = Bs[cur][k][nt + j];
#pragma unroll
            for (int i = 0; i < 4; i++)
#pragma unroll
                for (int j = 0; j < 4; j++)
                    acc[i][j] = fmaf(av[i], bv[j], acc[i][j]);
        }
        if (t + 1 < ntiles) {
            int nxt = cur ^ 1;
#pragma unroll
            for (int e = 0; e < 4; e++) {
                As[nxt][ra_c[e]][ra_r[e]] = ra[e];
                Bs[nxt][rb_r[e]][rb_c[e]] = rb[e];
            }
        }
        __syncthreads();
    }

#pragma unroll
    for (int i = 0; i < 4; i++) {
        int gm = m0 + mt + i;
        if (gm >= M) continue;
#pragma unroll
        for (int j = 0; j < 4; j++) {
            int gn = n0 + nt + j;
            if (gn >= N) continue;
            float v = alpha * acc[i][j];
            if (MIR == 0) {
                C[(long long)gm * ldc + gn] = v;
            } else if (MIR == 1) {
                C[(long long)gm * ldc + 256 + gn] = v;
                if (gn > 0) C[(long long)gm * ldc + 256 - gn] = -v;
            } else {
                C[(long long)(256 + gm) * ldc + gn] = v;
                if (gm > 0) C[(long long)(256 - gm) * ldc + gn] = -v;
            }
        }
    }
}

// ---------------------------------------------------------------------------
// Combined corner fold: cD -> Af = [A1f ; A2f] (516 x 516).
// ---------------------------------------------------------------------------
__global__ void k_foldA(const float2* __restrict__ cD, float* __restrict__ Af)
{
    int b = blockIdx.z;
    int kc = blockIdx.x * 32 + threadIdx.x;
    int kr = blockIdx.y * 8 + threadIdx.y;
    if (kc >= NK || kr >= NK) return;
    const float2* D = cD + (long long)b * NN;
    bool pc = (kc >= 1 && kc <= 255);
    bool pr = (kr >= 1 && kr <= 255);
    float2 z = make_float2(0.f, 0.f);
    float2 pp = D[(long long)(255 + kr) * NG + 255 + kc];
    float2 pm = pc ? D[(long long)(255 + kr) * NG + 255 - kc] : z;
    float2 mp = pr ? D[(long long)(255 - kr) * NG + 255 + kc] : z;
    float2 mm = (pc && pr) ? D[(long long)(255 - kr) * NG + 255 - kc] : z;
    float* a1 = Af + (long long)b * NAF + (long long)kr * NK2;
    float* a2 = Af + (long long)b * NAF + (long long)(NK + kr) * NK2;
    a1[kc]      = (pp.x + pm.x) + (mp.x + mm.x);
    a1[NK + kc] = -((pp.y - pm.y) + (mp.y - mm.y));
    a2[kc]      = (pp.y + pm.y) - (mp.y + mm.y);
    a2[NK + kc] = (pp.x - pm.x) - (mp.x - mm.x);
}

// ---------------------------------------------------------------------------
// wt*ik2 helper
// ---------------------------------------------------------------------------
DINLINE float2 wtik_apply(float2 c, float wrv, float wiv, int p, int q)
{
    float dp = (float)(p - 256), dq = (float)(q - 256);
    float s = dp * dp + dq * dq;
    const float pi2 = 9.869604401089358f;
    float ik = (s == 0.f) ? 1.f : 1.f / (pi2 * s);
    float2 rr;
    rr.x = (c.x * wrv - c.y * wiv) * ik;
    rr.y = (c.x * wiv + c.y * wrv) * ik;
    return rr;
}

// ---------------------------------------------------------------------------
// Composed 7x7 forward conv (real input) + wt*ik2. 2 px/thread.
// ---------------------------------------------------------------------------
__global__ __launch_bounds__(256)
void k_conv7f(const float* __restrict__ X, float2* __restrict__ Y,
              const float2* __restrict__ wf,
              const float* __restrict__ wtr, const float* __restrict__ wti)
{
    int b = blockIdx.z;
    __shared__ float2 ws[49];
    int t = threadIdx.y * 16 + threadIdx.x;
    if (t < 49) ws[t] = wf[b * 49 + t];
    __syncthreads();
    int q = blockIdx.x * 16 + threadIdx.x;
    int p0 = blockIdx.y * 32 + 2 * threadIdx.y;
    if (q >= NG || p0 >= NG) return;
    bool hasP1 = (p0 + 1 < NG);
    const float* Xb = X + (long long)b * NN;
    float2 a0 = make_float2(0.f, 0.f), a1 = make_float2(0.f, 0.f);
    int pB = blockIdx.y * 32, qB = blockIdx.x * 16;
    bool interior = (pB >= 3) && (pB + 34 <= NG - 1) && (qB >= 3) && (qB + 18 <= NG - 1);
    if (interior) {
#pragma unroll
        for (int r = 0; r < 8; r++) {
            int row = p0 - 3 + r;
            float xr[7];
#pragma unroll
            for (int c = 0; c < 7; c++) xr[c] = Xb[(long long)row * NG + q - 3 + c];
#pragma unroll
            for (int dx = 0; dx < 7; dx++) {
                if (r < 7) {
                    float2 w = ws[r * 7 + dx];
                    a0.x = fmaf(xr[dx], w.x, a0.x);
                    a0.y = fmaf(xr[dx], w.y, a0.y);
                }
                if (r >= 1) {
                    float2 w = ws[(r - 1) * 7 + dx];
                    a1.x = fmaf(xr[dx], w.x, a1.x);
                    a1.y = fmaf(xr[dx], w.y, a1.y);
                }
            }
        }
    } else {
#pragma unroll
        for (int r = 0; r < 8; r++) {
            int row = p0 - 3 + r;
            bool vr = (row >= 0 && row < NG);
            float xr[7];
#pragma unroll
            for (int c = 0; c < 7; c++) {
                int col = q - 3 + c;
                xr[c] = (vr && col >= 0 && col < NG) ? Xb[(long long)row * NG + col] : 0.f;
            }
#pragma unroll
            for (int dx = 0; dx < 7; dx++) {
                if (r < 7) {
                    float2 w = ws[r * 7 + dx];
                    a0.x = fmaf(xr[dx], w.x, a0.x);
                    a0.y = fmaf(xr[dx], w.y, a0.y);
                }
                if (r >= 1) {
                    float2 w = ws[(r - 1) * 7 + dx];
                    a1.x = fmaf(xr[dx], w.x, a1.x);
                    a1.y = fmaf(xr[dx], w.y, a1.y);
                }
            }
        }
    }
    float2* Yb = Y + (long long)b * NN;
    {
        long long o = (long long)b * NN + (long long)p0 * NG + q;
        Yb[(long long)p0 * NG + q] = wtik_apply(a0, wtr[o], wti[o], p0, q);
    }
    if (hasP1) {
        long long o = (long long)b * NN + (long long)(p0 + 1) * NG + q;
        Yb[(long long)(p0 + 1) * NG + q] = wtik_apply(a1, wtr[o], wti[o], p0 + 1, q);
    }
}

// ---------------------------------------------------------------------------
// Composed 7x7 backward conv (complex input), taps = conj(wf^T). 2 px/thread.
// ---------------------------------------------------------------------------
__global__ __launch_bounds__(256)
void k_conv7b(const float2* __restrict__ X, float2* __restrict__ Y,
              const float2* __restrict__ wf)
{
    int b = blockIdx.z;
    __shared__ float2 ws[49];
    int t = threadIdx.y * 16 + threadIdx.x;
    if (t < 49) {
        int dy = t / 7, dx = t % 7;
        float2 v = wf[b * 49 + dx * 7 + dy];
        ws[t] = make_float2(v.x, -v.y);
    }
    __syncthreads();
    int q = blockIdx.x * 16 + threadIdx.x;
    int p0 = blockIdx.y * 32 + 2 * threadIdx.y;
    if (q >= NG || p0 >= NG) return;
    bool hasP1 = (p0 + 1 < NG);
    const float2* Xb = X + (long long)b * NN;
    float2 a0 = make_float2(0.f, 0.f), a1 = make_float2(0.f, 0.f);
    int pB = blockIdx.y * 32, qB = blockIdx.x * 16;
    bool interior = (pB >= 3) && (pB + 34 <= NG - 1) && (qB >= 3) && (qB + 18 <= NG - 1);
    if (interior) {
#pragma unroll
        for (int r = 0; r < 8; r++) {
            int row = p0 - 3 + r;
            float2 xr[7];
#pragma unroll
            for (int c = 0; c < 7; c++) xr[c] = Xb[(long long)row * NG + q - 3 + c];
#pragma unroll
            for (int dx = 0; dx < 7; dx++) {
                if (r < 7) a0 = cmad(a0, xr[dx], ws[r * 7 + dx]);
                if (r >= 1) a1 = cmad(a1, xr[dx], ws[(r - 1) * 7 + dx]);
            }
        }
    } else {
#pragma unroll
        for (int r = 0; r < 8; r++) {
            int row = p0 - 3 + r;
            bool vr = (row >= 0 && row < NG);
            float2 xr[7];
#pragma unroll
            for (int c = 0; c < 7; c++) {
                int col = q - 3 + c;
                xr[c] = (vr && col >= 0 && col < NG)
                      ? Xb[(long long)row * NG + col] : make_float2(0.f, 0.f);
            }
#pragma unroll
            for (int dx = 0; dx < 7; dx++) {
                if (r < 7) a0 = cmad(a0, xr[dx], ws[r * 7 + dx]);
                if (r >= 1) a1 = cmad(a1, xr[dx], ws[(r - 1) * 7 + dx]);
            }
        }
    }
    float2* Yb = Y + (long long)b * NN;
    Yb[(long long)p0 * NG + q] = a0;
    if (hasP1) Yb[(long long)(p0 + 1) * NG + q] = a1;
}

// ---------------------------------------------------------------------------
// Strip conv: exact sequential 3x3 conv on a boundary frame of width FW.
// ---------------------------------------------------------------------------
template<int CO, int CI, int FW, bool REAL_IN, bool WTIK>
__global__ __launch_bounds__(256)
void k_conv_strip(const void* __restrict__ Xv, float2* __restrict__ Y,
                  const float* __restrict__ wr, const float* __restrict__ wi,
                  int conjt, const float* __restrict__ wtr,
                  const float* __restrict__ wti)
{
    int b = blockIdx.y;
    __shared__ float2 ws[CO * CI * 9];
    int t = threadIdx.x;
    if (t < CO * CI * 9) {
        int o = t / (CI * 9), rem = t % (CI * 9), i = rem / 9, tap = rem % 9;
        int dy = tap / 3, dx = tap % 3;
        long long widx;
        float sgn;
        if (conjt) { widx = ((long long)(b * CI + i) * CO + o) * 9 + dx * 3 + dy; sgn = -1.f; }
        else       { widx = ((long long)(b * CO + o) * CI + i) * 9 + dy * 3 + dx; sgn =  1.f; }
        ws[t] = make_float2(wr[widx], sgn * wi[widx]);
    }
    __syncthreads();

    const int nTop = FW * NG;
    const int nSide = (NG - 2 * FW) * FW;
    const int total = 2 * nTop + 2 * nSide;
    int idx = blockIdx.x * 256 + t;
    if (idx >= total) return;
    int p, q;
    if (idx < nTop)            { p = idx / NG; q = idx - p * NG; }
    else if (idx < 2 * nTop)   { int k2 = idx - nTop; p = NG - FW + k2 / NG; q = k2 % NG; }
    else if (idx < 2 * nTop + nSide) { int k2 = idx - 2 * nTop; p = FW + k2 / FW; q = k2 % FW; }
    else                       { int k2 = idx - 2 * nTop - nSide; p = FW + k2 / FW; q = NG - FW + k2 % FW; }

    float2 acc[CO];
#pragma unroll
    for (int o = 0; o < CO; o++) acc[o] = make_float2(0.f, 0.f);
#pragma unroll
    for (int i = 0; i < CI; i++) {
#pragma unroll
        for (int dy = 0; dy < 3; dy++) {
            int ii = p + dy - 1;
#pragma unroll
            for (int dx = 0; dx < 3; dx++) {
                int jj = q + dx - 1;
                float2 xv = make_float2(0.f, 0.f);
                if (ii >= 0 && ii < NG && jj >= 0 && jj < NG) {
                    if (REAL_IN) {
                        const float* Xb = (const float*)Xv + (long long)b * NN;
                        xv.x = Xb[(long long)ii * NG + jj];
                    } else {
                        const float2* Xb = (const float2*)Xv + (long long)b * CI * NN;
                        xv = Xb[(long long)i * NN + (long long)ii * NG + jj];
                    }
                }
                int tap = dy * 3 + dx;
#pragma unroll
                for (int o = 0; o < CO; o++)
                    acc[o] = cmad(acc[o], xv, ws[(o * CI + i) * 9 + tap]);
            }
        }
    }
    float2* Yb = Y + (long long)b * CO * NN;
    long long po = (long long)p * NG + q;
    if (WTIK) {
        long long o = (long long)b * NN + po;
        Yb[po] = wtik_apply(acc[0], wtr[o], wti[o], p, q);
    } else {
#pragma unroll
        for (int o = 0; o < CO; o++) Yb[(long long)o * NN + po] = acc[o];
    }
}

// ---------------------------------------------------------------------------
// Reductions (deterministic, double accumulation)
// ---------------------------------------------------------------------------
__global__ __launch_bounds__(256)
void k_alpha_part(const float* __restrict__ r, const float* __restrict__ e,
                  const float* __restrict__ a, double* __restrict__ p1,
                  double* __restrict__ p2)
{
    int b = blockIdx.y;
    const float* rb = r + (long long)b * NN;
    const float* eb = e + (long long)b * NN;
    const float* ab = a + (long long)b * NCC;
    double num = 0.0, den = 0.0;
    for (long long idx = (long long)blockIdx.x * 256 + threadIdx.x; idx < NN;
         idx += (long long)gridDim.x * 256) {
        int i = (int)(idx / NG), j = (int)(idx - (long long)i * NG);
        float ev = eb[idx];
        num += (double)(rb[idx] * ev);
        if (i > 0 && j > 0 && i < NG - 1 && j < NG - 1) {
            float d = darcy_at(eb, ab, i, j);
            den += (double)(d * ev);
        }
    }
    __shared__ double s1[256], s2[256];
    int t = threadIdx.x;
    s1[t] = num; s2[t] = den;
    __syncthreads();
    for (int s = 128; s > 0; s >>= 1) {
        if (t < s) { s1[t] += s1[t + s]; s2[t] += s2[t + s]; }
        __syncthreads();
    }
    if (t == 0) { p1[b * NBLK_A + blockIdx.x] = s1[0]; p2[b * NBLK_A + blockIdx.x] = s2[0]; }
}

__global__ void k_alpha_fin(const double* __restrict__ p1,
                            const double* __restrict__ p2,
                            float* __restrict__ alpha)
{
    int b = blockIdx.x;
    __shared__ double s1[256], s2[256];
    double n = 0.0, d = 0.0;
    for (int i = threadIdx.x; i < NBLK_A; i += 256) {
        n += p1[b * NBLK_A + i]; d += p2[b * NBLK_A + i];
    }
    int t = threadIdx.x;
    s1[t] = n; s2[t] = d;
    __syncthreads();
    for (int s = 128; s > 0; s >>= 1) {
        if (t < s) { s1[t] += s1[t + s]; s2[t] += s2[t + s]; }
        __syncthreads();
    }
    if (t == 0) alpha[b] = (float)(s1[0] / s2[0]);
}

__global__ void k_update(float* __restrict__ x, const float* __restrict__ e,
                         const float* __restrict__ alpha)
{
    int b = blockIdx.z;
    int j = blockIdx.x * 16 + threadIdx.x + 1;
    int i = blockIdx.y * 16 + threadIdx.y + 1;
    if (i > NI || j > NI) return;
    long long o = (long long)b * NN + (long long)i * NG + j;
    x[o] = fmaf(alpha[b], e[o], x[o]);
}

// Fused final residual + norm partial reduction: rv = f - A(x) computed on
// the fly, summation order identical to the old (resid -> norm_part) pair.
__global__ __launch_bounds__(256)
void k_resnorm(const float* __restrict__ x, const float* __restrict__ f,
               const float* __restrict__ a,
               double* __restrict__ p1, double* __restrict__ p2)
{
    double sr = 0.0, sf = 0.0;
    long long tot = (long long)NB * NN;
    for (long long idx = (long long)blockIdx.x * 256 + threadIdx.x; idx < tot;
         idx += (long long)gridDim.x * 256) {
        int b = (int)(idx / NN);
        long long rem = idx - (long long)b * NN;
        int i = (int)(rem / NG), j = (int)(rem - (long long)i * NG);
        float fv = f[idx];
        float d = 0.f;
        if (i > 0 && j > 0 && i < NG - 1 && j < NG - 1)
            d = darcy_at(x + (long long)b * NN, a + (long long)b * NCC, i, j);
        float rv = fv - d;
        sr += (double)rv * rv;
        sf += (double)fv * fv;
    }
    __shared__ double s1[256], s2[256];
    int t = threadIdx.x;
    s1[t] = sr; s2[t] = sf;
    __syncthreads();
    for (int s = 128; s > 0; s >>= 1) {
        if (t < s) { s1[t] += s1[t + s]; s2[t] += s2[t + s]; }
        __syncthreads();
    }
    if (t == 0) { p1[blockIdx.x] = s1[0]; p2[blockIdx.x] = s2[0]; }
}

__global__ void k_norm_fin(const double* __restrict__ p1,
                           const double* __restrict__ p2,
                           float* __restrict__ out)
{
    __shared__ double s1[256], s2[256];
    double a = 0.0, b = 0.0;
    for (int i = threadIdx.x; i < NBLK_N; i += 256) { a += p1[i]; b += p2[i]; }
    int t = threadIdx.x;
    s1[t] = a; s2[t] = b;
    __syncthreads();
    for (int s = 128; s > 0; s >>= 1) {
        if (t < s) { s1[t] += s1[t + s]; s2[t] += s2[t + s]; }
        __syncthreads();
    }
    if (t == 0) out[0] = (float)sqrt(s1[0] / s2[0]);
}

// ---------------------------------------------------------------------------
// Host orchestration
// ---------------------------------------------------------------------------
template<typename T>
static T* sym_addr(const void* sym)
{
    void* p = nullptr;
    cudaGetSymbolAddress(&p, sym);
    return (T*)p;
}

static inline int strip_blocks(int FW)
{
    int nTop = FW * NG, nSide = (NG - 2 * FW) * FW;
    int total = 2 * nTop + 2 * nSide;
    return (total + 255) / 256;
}

extern "C" void kernel_launch(void* const* d_in, const int* in_sizes, int n_in,
                              void* d_out, int out_size)
{
    const float* f    = (const float*)d_in[0];
    const float* coef = (const float*)d_in[1];
    const float* w1r = (const float*)d_in[3];
    const float* w1i = (const float*)d_in[4];
    const float* w2r = (const float*)d_in[5];
    const float* w2i = (const float*)d_in[6];
    const float* w3r = (const float*)d_in[7];
    const float* w3i = (const float*)d_in[8];
    const float* wtr = (const float*)d_in[9];
    const float* wti = (const float*)d_in[10];

    float*  x    = sym_addr<float>(g_x);
    float*  x2   = sym_addr<float>(g_x2);
    float*  r    = sym_addr<float>(g_r);
    float*  e    = sym_addr<float>(g_e);
    float*  rh   = sym_addr<float>(g_rh);
    float*  dinv = sym_addr<float>(g_dinv);
    float*  S    = sym_addr<float>(g_S);
    float*  St   = sym_addr<float>(g_St);
    float*  U    = sym_addr<float>(g_U);
    float2* cA   = sym_addr<float2>(g_cA);
    float2* cB   = sym_addr<float2>(g_cB);
    float2* cC   = sym_addr<float2>(g_cC);
    float2* cD   = sym_addr<float2>(g_cD);
    float2* wf   = sym_addr<float2>(g_wf);
    float*  Af   = sym_addr<float>(g_Af);
    float*  F    = sym_addr<float>(g_F);
    float*  Bm   = sym_addr<float>(g_Bm);
    float*  Em   = sym_addr<float>(g_Em);
    double* pd1  = sym_addr<double>(g_pd1);
    double* pd2  = sym_addr<double>(g_pd2);
    float*  alph = sym_addr<float>(g_alpha);

    dim3 blk2(16, 16);
    dim3 gInt((NI + 15) / 16, (NI + 15) / 16, NB);
    dim3 gConv((NG + 15) / 16, (NG + 31) / 32, NB);
    dim3 gJac((NG + 31) / 32, (NG + 31) / 32, NB);

    dim3 gS5(strip_blocks(5), NB);
    dim3 gS4(strip_blocks(4), NB);
    dim3 gS3(strip_blocks(3), NB);

    dim3 blkF(32, 8);
    dim3 gFo((NK + 31) / 32, (NK + 7) / 8, NB);

    // ---- setup (1 segmented kernel + conv composition) ----
    {
        long long total = (long long)NB * NN + (long long)NG * NI
                        + (long long)NK2 * NI + (long long)NI * NK2
                        + (long long)NB * NII;
        k_setup<<<(int)((total + 255) / 256), 256>>>(x, x2, e, S, St, Bm, Em,
                                                     coef, dinv);
        k_compose<<<NB, 64>>>(w1r, w1i, w2r, w2i, w3r, w3i, wf);
    }

    for (int step = 0; step < KSTEPS; step++) {
        // ---- 10 Jacobi sweeps (2 fused kernels) + residual.
        //      Step 1 folds the pending x += alpha*e update into the load.
        if (step == 0)
            k_jacobi5<false, false><<<gJac, 256>>>(x, x2, f, coef, dinv,
                                                   nullptr, nullptr, nullptr);
        else
            k_jacobi5<false, true ><<<gJac, 256>>>(x, x2, f, coef, dinv,
                                                   nullptr, e, alph);
        k_jacobi5<true, false><<<gJac, 256>>>(x2, x, f, coef, dinv, r,
                                              nullptr, nullptr);

        // ---- forward sine transform (odd symmetry fused in epilogue) ----
        {
            dim3 g((257 + 63) / 64, (NI + 63) / 64, NB);
            k_sgemm<1><<<g, 256>>>(r + NG + 1, NG, NN,
                                   St + 256, NG, 0,
                                   U, NG, NIG,
                                   NI, 257, NI, 1.f);
        }
        {
            dim3 g((NG + 63) / 64, (257 + 63) / 64, NB);
            k_sgemm<2><<<g, 256>>>(S + 256 * NI, NI, 0,
                                   U, NG, NIG,
                                   rh, NG, NN,
                                   257, NG, NI, -1.f / (512.f * 512.f));
        }

        // ---- forward conv chain: composed 7x7 + exact ring correction ----
        k_conv7f<<<gConv, blk2>>>(rh, cC, wf, wtr, wti);
        k_conv_strip<4, 1, 5, true,  false><<<gS5, 256>>>(rh, cA, w1r, w1i, 0, nullptr, nullptr);
        k_conv_strip<4, 4, 4, false, false><<<gS4, 256>>>(cA, cB, w2r, w2i, 0, nullptr, nullptr);
        k_conv_strip<1, 4, 3, false, true ><<<gS3, 256>>>(cB, cC, w3r, w3i, 0, wtr, wti);

        // ---- backward conv chain: composed conj(wf^T) + ring correction ----
        k_conv7b<<<gConv, blk2>>>(cC, cD, wf);
        k_conv_strip<4, 1, 5, false, false><<<gS5, 256>>>(cC, cA, w3r, w3i, 1, nullptr, nullptr);
        k_conv_strip<4, 4, 4, false, false><<<gS4, 256>>>(cA, cB, w2r, w2i, 1, nullptr, nullptr);
        k_conv_strip<1, 4, 3, false, false><<<gS3, 256>>>(cB, cD, w1r, w1i, 1, nullptr, nullptr);

        // ---- inverse transform: corner-fold then 2 real GEMMs ----
        k_foldA<<<gFo, blkF>>>(cD, Af);
        {
            dim3 g((NI + 63) / 64, (NK2 + 63) / 64, NB);
            k_sgemm<0><<<g, 256>>>(Af, NK2, NAF, Bm, NI, 0, F, NI, NF,
                                   NK2, NI, NK2, 1.f);
        }
        {
            dim3 g((NI + 63) / 64, (NI + 63) / 64, NB);
            k_sgemm<0><<<g, 256>>>(Em, NK2, 0, F, NI, NF, e + NG + 1, NG, NN,
                                   NI, NI, NK2, 1.f);
        }

        // ---- alpha; the x update is fused into the consumer kernels ----
        {
            dim3 g(NBLK_A, NB);
            k_alpha_part<<<g, 256>>>(r, e, coef, pd1, pd2);
            k_alpha_fin<<<NB, 256>>>(pd1, pd2, alph);
        }
        if (step == KSTEPS - 1) {
            // final: apply last update explicitly, then fused resid+norm
            k_update<<<gInt, blk2>>>(x, e, alph);
        }
    }

    // ---- final relative residual norm (fused resid + partial reduction) ----
    k_resnorm<<<NBLK_N, 256>>>(x, f, coef, pd1, pd2);
    k_norm_fin<<<1, 256>>>(pd1, pd2, (float*)d_out);
}